// round 10
// baseline (speedup 1.0000x reference)
#include <cuda_runtime.h>
#include <cuda_bf16.h>
#include <math.h>
#include <float.h>
#include <stdint.h>

#define BATCH 2
#define CCH   512
#define HW    4096
#define NGRP  32
#define CPG   16
#define GRPELEM (CPG * HW)   // 65536

#define PMK 20    // padded row len for [row][k16] fp32 tiles (128 x 16)
#define PKM 136   // padded row len for [k16][col] fp32 tiles (16 x 128)

// per-stage float counts (tf32 kernels)
#define QKV_STG (16 * PKM + 128 * PMK)
#define SC_STG  (2 * 128 * PMK)
#define QKV_DYN (3 * QKV_STG * 4)
#define SC_DYN  (3 * SC_STG * 4)

// bf16 O GEMM geometry: k-chunk 32, rows padded to 20 words (40 bf16, 80 B)
#define OROWW 20
#define O_STG_WORDS (2 * 128 * OROWW)
#define O_STG_BYTES (O_STG_WORDS * 4)
#define O_DYN_B (3 * O_STG_BYTES)

#define ZROWBLK 64   // rows per zcolsum CTA

// ---------------- scratch (static device globals; no allocation) -------------
__device__ float         g_hn  [(size_t)BATCH * CCH * HW];  // normed [b][c][n]
__device__ float         g_q   [(size_t)BATCH * HW * CCH];  // [b][i][c]
__device__ float         g_k   [(size_t)BATCH * HW * CCH];  // [b][j][c]
__device__ float         g_vt  [(size_t)BATCH * CCH * HW];  // [b][c][i] fp32
__device__ __nv_bfloat16 g_vb  [(size_t)BATCH * CCH * HW];  // [b][c][i] bf16 * 1/Z_i
__device__ __nv_bfloat16 g_s   [(size_t)BATCH * HW * HW];   // E'[j][i] = exp(scale*S^T)
__device__ float         g_o   [(size_t)BATCH * HW * CCH];  // attn out [b][j][c]
__device__ float         g_zp  [(size_t)BATCH * (HW / ZROWBLK) * HW]; // partials
__device__ float         g_z   [(size_t)BATCH * HW];        // 1/Z_i

// ------------------------------ helpers --------------------------------------
__device__ __forceinline__ void mma8(float* d, const unsigned* a, const unsigned* b) {
    asm volatile(
        "mma.sync.aligned.m16n8k8.row.col.f32.tf32.tf32.f32 "
        "{%0,%1,%2,%3}, {%4,%5,%6,%7}, {%8,%9}, {%0,%1,%2,%3};\n"
        : "+f"(d[0]), "+f"(d[1]), "+f"(d[2]), "+f"(d[3])
        : "r"(a[0]), "r"(a[1]), "r"(a[2]), "r"(a[3]), "r"(b[0]), "r"(b[1]));
}
__device__ __forceinline__ void mma16(float* d, const unsigned* a, const unsigned* b) {
    asm volatile(
        "mma.sync.aligned.m16n8k16.row.col.f32.bf16.bf16.f32 "
        "{%0,%1,%2,%3}, {%4,%5,%6,%7}, {%8,%9}, {%0,%1,%2,%3};\n"
        : "+f"(d[0]), "+f"(d[1]), "+f"(d[2]), "+f"(d[3])
        : "r"(a[0]), "r"(a[1]), "r"(a[2]), "r"(a[3]), "r"(b[0]), "r"(b[1]));
}
__device__ __forceinline__ unsigned sptr(const void* p) {
    return (unsigned)__cvta_generic_to_shared(p);
}
#define CPA16(dst, src) asm volatile("cp.async.ca.shared.global [%0], [%1], 16;\n" :: "r"(dst), "l"(src))
#define CPCOMMIT()      asm volatile("cp.async.commit_group;\n")
#define CPWAIT1()       asm volatile("cp.async.wait_group 1;\n" ::: "memory")
__device__ __forceinline__ unsigned fu(float f) { return __float_as_uint(f); }

// ---------------------------- GroupNorm --------------------------------------
__global__ void groupnorm_kernel(const float* __restrict__ x,
                                 const float* __restrict__ gw,
                                 const float* __restrict__ gb) {
    int b = blockIdx.x >> 5;
    int g = blockIdx.x & 31;
    const float4* xp = (const float4*)(x    + ((size_t)b * CCH + g * CPG) * HW);
    float4*       op = (float4*)      (g_hn + ((size_t)b * CCH + g * CPG) * HW);
    int tid = threadIdx.x;

    float s = 0.f, ss = 0.f;
    for (int i = tid; i < GRPELEM / 4; i += 256) {
        float4 v = xp[i];
        s  += v.x + v.y + v.z + v.w;
        ss += v.x * v.x + v.y * v.y + v.z * v.z + v.w * v.w;
    }
    __shared__ float shs[8], shss[8];
    #pragma unroll
    for (int o = 16; o; o >>= 1) {
        s  += __shfl_xor_sync(0xffffffffu, s,  o);
        ss += __shfl_xor_sync(0xffffffffu, ss, o);
    }
    if ((tid & 31) == 0) { shs[tid >> 5] = s; shss[tid >> 5] = ss; }
    __syncthreads();
    __shared__ float sm, sr;
    if (tid == 0) {
        float S = 0.f, SS = 0.f;
        #pragma unroll
        for (int i = 0; i < 8; i++) { S += shs[i]; SS += shss[i]; }
        float mean = S / (float)GRPELEM;
        float var  = SS / (float)GRPELEM - mean * mean;
        sm = mean;
        sr = rsqrtf(var + 1e-6f);
    }
    __syncthreads();
    float mean = sm, rstd = sr;
    for (int i = tid; i < GRPELEM / 4; i += 256) {
        int cl = i >> 10;
        float sc = gw[g * CPG + cl] * rstd;
        float sh = gb[g * CPG + cl] - mean * sc;
        float4 v = xp[i];
        v.x = v.x * sc + sh; v.y = v.y * sc + sh;
        v.z = v.z * sc + sh; v.w = v.w * sc + sh;
        op[i] = v;
    }
}

// ---- frag loaders (fp32/tf32 tiles) -----------------------------------------
#define LOAD_AF_KM(af, Ab, kk, wm) do {                                        \
    _Pragma("unroll")                                                          \
    for (int mi = 0; mi < 4; mi++) {                                           \
        int mb = (wm) + mi * 16 + g;                                           \
        (af)[mi][0] = fu((Ab)[((kk) + tig) * PKM + mb]);                       \
        (af)[mi][1] = fu((Ab)[((kk) + tig) * PKM + mb + 8]);                   \
        (af)[mi][2] = fu((Ab)[((kk) + tig + 4) * PKM + mb]);                   \
        (af)[mi][3] = fu((Ab)[((kk) + tig + 4) * PKM + mb + 8]);               \
    } } while (0)
#define LOAD_AF_MK(af, Ab, kk, wm) do {                                        \
    _Pragma("unroll")                                                          \
    for (int mi = 0; mi < 4; mi++) {                                           \
        int mb = (wm) + mi * 16 + g;                                           \
        (af)[mi][0] = fu((Ab)[mb * PMK + (kk) + tig]);                         \
        (af)[mi][1] = fu((Ab)[(mb + 8) * PMK + (kk) + tig]);                   \
        (af)[mi][2] = fu((Ab)[mb * PMK + (kk) + tig + 4]);                     \
        (af)[mi][3] = fu((Ab)[(mb + 8) * PMK + (kk) + tig + 4]);               \
    } } while (0)
#define LOAD_BF_MK(bf, Bb, kk, wn) do {                                        \
    _Pragma("unroll")                                                          \
    for (int nj = 0; nj < 4; nj++) {                                           \
        int nb = (wn) + nj * 8 + g;                                            \
        (bf)[nj][0] = fu((Bb)[nb * PMK + (kk) + tig]);                         \
        (bf)[nj][1] = fu((Bb)[nb * PMK + (kk) + tig + 4]);                     \
    } } while (0)
#define MMA_ALL8(acc, af, bf) do {                                             \
    _Pragma("unroll")                                                          \
    for (int mi = 0; mi < 4; mi++)                                             \
        _Pragma("unroll")                                                      \
        for (int nj = 0; nj < 4; nj++) mma8((acc)[mi][nj], (af)[mi], (bf)[nj]);\
    } while (0)

// -------- QKV GEMM (merged): C[m,n] = sum_k A[k,m] * W[n,k] + bias[n] --------
__global__ __launch_bounds__(256, 2)
void qkv_mma_kernel(const float* __restrict__ wq, const float* __restrict__ bq,
                    const float* __restrict__ wk, const float* __restrict__ bk,
                    const float* __restrict__ wv, const float* __restrict__ bv) {
    extern __shared__ float smem[];
    int b = blockIdx.z;
    int which = blockIdx.y >> 2;
    int n0 = (blockIdx.y & 3) * 128, m0 = blockIdx.x * 128;
    const float* Wt   = which == 0 ? wq : which == 1 ? wk : wv;
    const float* bias = which == 0 ? bq : which == 1 ? bk : bv;
    const float* Ag = g_hn + (size_t)b * CCH * HW + m0;
    int tid = threadIdx.x;
    int lane = tid & 31, warp = tid >> 5;
    int g = lane >> 2, tig = lane & 3;
    int wm = (warp >> 2) * 64, wn = (warp & 3) * 32;
    int arow = tid >> 5, acol = (tid & 31) << 2;
    int brow = tid >> 2, bcol = (tid & 3) << 2;

    float acc[4][4][4];
    #pragma unroll
    for (int i = 0; i < 4; i++)
        #pragma unroll
        for (int j = 0; j < 4; j++)
            #pragma unroll
            for (int t = 0; t < 4; t++) acc[i][j][t] = 0.f;

    const int NT = CCH / 16;
    #pragma unroll
    for (int s = 0; s < 2; s++) {
        float* As = smem + s * QKV_STG;
        float* Bs = As + 16 * PKM;
        #pragma unroll
        for (int rr = 0; rr < 2; rr++) {
            int r = arow + rr * 8;
            CPA16(sptr(&As[r * PKM + acol]), Ag + (size_t)(s * 16 + r) * HW + acol);
        }
        #pragma unroll
        for (int rr = 0; rr < 2; rr++) {
            int r = brow + rr * 64;
            CPA16(sptr(&Bs[r * PMK + bcol]), Wt + (size_t)(n0 + r) * CCH + s * 16 + bcol);
        }
        CPCOMMIT();
    }
    for (int kt = 0; kt < NT; kt++) {
        CPWAIT1();
        __syncthreads();
        const float* Ab = smem + (kt % 3) * QKV_STG;
        const float* Bb = Ab + 16 * PKM;
        unsigned af[4][4], bf[4][2];
        LOAD_AF_KM(af, Ab, 0, wm);
        LOAD_BF_MK(bf, Bb, 0, wn);
        MMA_ALL8(acc, af, bf);
        LOAD_AF_KM(af, Ab, 8, wm);
        LOAD_BF_MK(bf, Bb, 8, wn);
        MMA_ALL8(acc, af, bf);
        int nk = kt + 2;
        if (nk < NT) {
            float* As = smem + (nk % 3) * QKV_STG;
            float* Bs = As + 16 * PKM;
            #pragma unroll
            for (int rr = 0; rr < 2; rr++) {
                int r = arow + rr * 8;
                CPA16(sptr(&As[r * PKM + acol]), Ag + (size_t)(nk * 16 + r) * HW + acol);
            }
            #pragma unroll
            for (int rr = 0; rr < 2; rr++) {
                int r = brow + rr * 64;
                CPA16(sptr(&Bs[r * PMK + bcol]), Wt + (size_t)(n0 + r) * CCH + nk * 16 + bcol);
            }
        }
        CPCOMMIT();
    }
    if (which == 2) {
        float* Vt = g_vt + (size_t)b * CCH * HW;
        #pragma unroll
        for (int mi = 0; mi < 4; mi++)
            #pragma unroll
            for (int nj = 0; nj < 4; nj++) {
                int r = m0 + wm + mi * 16 + g;
                int c = n0 + wn + nj * 8 + 2 * tig;
                float bv0 = bias[c], bv1 = bias[c + 1];
                Vt[(size_t)c * HW + r]           = acc[mi][nj][0] + bv0;
                Vt[(size_t)(c + 1) * HW + r]     = acc[mi][nj][1] + bv1;
                Vt[(size_t)c * HW + r + 8]       = acc[mi][nj][2] + bv0;
                Vt[(size_t)(c + 1) * HW + r + 8] = acc[mi][nj][3] + bv1;
            }
    } else {
        float* Cp = (which == 0 ? g_q : g_k) + (size_t)b * HW * CCH;
        #pragma unroll
        for (int mi = 0; mi < 4; mi++)
            #pragma unroll
            for (int nj = 0; nj < 4; nj++) {
                int r = m0 + wm + mi * 16 + g;
                int c = n0 + wn + nj * 8 + 2 * tig;
                float bv0 = bias[c], bv1 = bias[c + 1];
                *(float2*)&Cp[(size_t)r * CCH + c] =
                    make_float2(acc[mi][nj][0] + bv0, acc[mi][nj][1] + bv1);
                *(float2*)&Cp[(size_t)(r + 8) * CCH + c] =
                    make_float2(acc[mi][nj][2] + bv0, acc[mi][nj][3] + bv1);
            }
    }
}

// -------- Scores (transposed): E'[j,i] = exp(scale * K_j . Q_i) -> bf16 ------
__global__ __launch_bounds__(256, 3)
void scores_mma_kernel() {
    extern __shared__ float smem[];
    int b = blockIdx.z;
    const float* Ag = g_k + (size_t)b * HW * CCH + (size_t)blockIdx.x * 128 * CCH; // m = j
    const float* Bg = g_q + (size_t)b * HW * CCH + (size_t)blockIdx.y * 128 * CCH; // n = i
    int tid = threadIdx.x;
    int lane = tid & 31, warp = tid >> 5;
    int g = lane >> 2, tig = lane & 3;
    int wm = (warp >> 2) * 64, wn = (warp & 3) * 32;
    int brow = tid >> 2, bcol = (tid & 3) << 2;

    float acc[4][4][4];
    #pragma unroll
    for (int i = 0; i < 4; i++)
        #pragma unroll
        for (int j = 0; j < 4; j++)
            #pragma unroll
            for (int t = 0; t < 4; t++) acc[i][j][t] = 0.f;

    const int NT = CCH / 16;
    #pragma unroll
    for (int s = 0; s < 2; s++) {
        float* As = smem + s * SC_STG;
        float* Bs = As + 128 * PMK;
        #pragma unroll
        for (int rr = 0; rr < 2; rr++) {
            int r = brow + rr * 64;
            CPA16(sptr(&As[r * PMK + bcol]), Ag + (size_t)r * CCH + s * 16 + bcol);
            CPA16(sptr(&Bs[r * PMK + bcol]), Bg + (size_t)r * CCH + s * 16 + bcol);
        }
        CPCOMMIT();
    }
    for (int kt = 0; kt < NT; kt++) {
        CPWAIT1();
        __syncthreads();
        const float* Ab = smem + (kt % 3) * SC_STG;
        const float* Bb = Ab + 128 * PMK;
        unsigned af[4][4], bf[4][2];
        LOAD_AF_MK(af, Ab, 0, wm);
        LOAD_BF_MK(bf, Bb, 0, wn);
        MMA_ALL8(acc, af, bf);
        LOAD_AF_MK(af, Ab, 8, wm);
        LOAD_BF_MK(bf, Bb, 8, wn);
        MMA_ALL8(acc, af, bf);
        int nk = kt + 2;
        if (nk < NT) {
            float* As = smem + (nk % 3) * SC_STG;
            float* Bs = As + 128 * PMK;
            #pragma unroll
            for (int rr = 0; rr < 2; rr++) {
                int r = brow + rr * 64;
                CPA16(sptr(&As[r * PMK + bcol]), Ag + (size_t)r * CCH + nk * 16 + bcol);
                CPA16(sptr(&Bs[r * PMK + bcol]), Bg + (size_t)r * CCH + nk * 16 + bcol);
            }
        }
        CPCOMMIT();
    }
    const float scale = 0.04419417382415922f;   // 512^-0.5
    __nv_bfloat16* Cp = g_s + (size_t)b * HW * HW;
    int m0 = blockIdx.x * 128, n0 = blockIdx.y * 128;
    #pragma unroll
    for (int mi = 0; mi < 4; mi++)
        #pragma unroll
        for (int nj = 0; nj < 4; nj++) {
            int r = m0 + wm + mi * 16 + g;
            int c = n0 + wn + nj * 8 + 2 * tig;
            *(__nv_bfloat162*)&Cp[(size_t)r * HW + c] =
                __floats2bfloat162_rn(__expf(acc[mi][nj][0] * scale),
                                      __expf(acc[mi][nj][1] * scale));
            *(__nv_bfloat162*)&Cp[(size_t)(r + 8) * HW + c] =
                __floats2bfloat162_rn(__expf(acc[mi][nj][2] * scale),
                                      __expf(acc[mi][nj][3] * scale));
        }
}

// ------- column sums of E' stage 1: each CTA sums 64 rows x 512 cols ---------
__global__ void zcolsum_kernel() {
    int b = blockIdx.z;
    const __nv_bfloat162* S = (const __nv_bfloat162*)(g_s + (size_t)b * HW * HW);
    int t = threadIdx.x;
    size_t rowstride = HW / 2;
    const __nv_bfloat162* p = S + (size_t)(blockIdx.y * ZROWBLK) * rowstride
                                + blockIdx.x * 256 + t;
    float sx[8], sy[8];
    #pragma unroll
    for (int u = 0; u < 8; u++) { sx[u] = 0.f; sy[u] = 0.f; }
    #pragma unroll
    for (int jj = 0; jj < ZROWBLK / 8; jj++) {
        #pragma unroll
        for (int u = 0; u < 8; u++) {
            float2 v = __bfloat1622float2(p[(size_t)(jj * 8 + u) * rowstride]);
            sx[u] += v.x; sy[u] += v.y;
        }
    }
    float fx = (sx[0] + sx[1]) + (sx[2] + sx[3]) + ((sx[4] + sx[5]) + (sx[6] + sx[7]));
    float fy = (sy[0] + sy[1]) + (sy[2] + sy[3]) + ((sy[4] + sy[5]) + (sy[6] + sy[7]));
    float* zp = g_zp + ((size_t)(b * (HW / ZROWBLK) + blockIdx.y)) * HW
              + (size_t)(blockIdx.x * 256 + t) * 2;
    zp[0] = fx; zp[1] = fy;
}

// ------- stage 2: combine partials, reciprocal -------------------------------
__global__ void zfin_kernel() {
    int idx = blockIdx.x * 256 + threadIdx.x;   // < BATCH*HW
    int b = idx >> 12, i = idx & (HW - 1);
    const float* zp = g_zp + (size_t)b * (HW / ZROWBLK) * HW + i;
    float s0 = 0.f, s1 = 0.f, s2 = 0.f, s3 = 0.f;
    #pragma unroll
    for (int p = 0; p < HW / ZROWBLK; p += 4) {
        s0 += zp[(size_t)(p + 0) * HW];
        s1 += zp[(size_t)(p + 1) * HW];
        s2 += zp[(size_t)(p + 2) * HW];
        s3 += zp[(size_t)(p + 3) * HW];
    }
    g_z[idx] = 1.f / ((s0 + s1) + (s2 + s3));
}

// ------- V-hat: g_vb[c][i] = bf16(g_vt[c][i] * g_z[i]) -----------------------
__global__ void vscale_kernel() {
    size_t idx4 = (size_t)blockIdx.x * 256 + threadIdx.x;
    int b = (int)(idx4 / ((size_t)CCH * (HW / 4)));
    size_t rem = idx4 - (size_t)b * CCH * (HW / 4);
    int i4 = (int)(rem % (HW / 4));
    float4 v = ((const float4*)g_vt)[idx4];
    float4 z = ((const float4*)g_z)[(size_t)b * (HW / 4) + i4];
    __nv_bfloat162* o = ((__nv_bfloat162*)g_vb) + idx4 * 2;
    o[0] = __floats2bfloat162_rn(v.x * z.x, v.y * z.y);
    o[1] = __floats2bfloat162_rn(v.z * z.z, v.w * z.w);
}

// ------ O GEMM (bf16): O[j,c] = sum_i E'[j,i] * Vhat[c,i] --------------------
__global__ __launch_bounds__(256, 2)
void o_bf16_kernel() {
    extern __shared__ unsigned osm[];
    int b = blockIdx.z;
    const __nv_bfloat16* Ag = g_s  + (size_t)b * HW * HW + (size_t)(blockIdx.x * 128) * HW;
    const __nv_bfloat16* Bg = g_vb + (size_t)b * CCH * HW + (size_t)(blockIdx.y * 128) * HW;
    int tid = threadIdx.x;
    int lane = tid & 31, warp = tid >> 5;
    int g = lane >> 2, tig = lane & 3;
    int wm = (warp >> 2) * 64, wn = (warp & 3) * 32;
    int lrow = tid >> 1, lh = tid & 1;
    uint32_t sbase = sptr(osm);

    float acc[4][4][4];
    #pragma unroll
    for (int i = 0; i < 4; i++)
        #pragma unroll
        for (int j = 0; j < 4; j++)
            #pragma unroll
            for (int t = 0; t < 4; t++) acc[i][j][t] = 0.f;

    const int NC = HW / 32;
    #pragma unroll
    for (int s = 0; s < 2; s++) {
        uint32_t st = sbase + s * O_STG_BYTES;
        const __nv_bfloat16* as = Ag + (size_t)lrow * HW + s * 32 + lh * 16;
        const __nv_bfloat16* bs = Bg + (size_t)lrow * HW + s * 32 + lh * 16;
        CPA16(st + lrow * 80 + lh * 32,              as);
        CPA16(st + lrow * 80 + lh * 32 + 16,         as + 8);
        CPA16(st + 10240 + lrow * 80 + lh * 32,      bs);
        CPA16(st + 10240 + lrow * 80 + lh * 32 + 16, bs + 8);
        CPCOMMIT();
    }
    for (int kt = 0; kt < NC; kt++) {
        CPWAIT1();
        __syncthreads();
        const unsigned* At = osm + (kt % 3) * O_STG_WORDS;
        const unsigned* Bt = At + 128 * OROWW;
        #pragma unroll
        for (int kk = 0; kk < 2; kk++) {
            unsigned af[4][4], bf[4][2];
            #pragma unroll
            for (int mi = 0; mi < 4; mi++) {
                int mb = wm + mi * 16 + g;
                af[mi][0] = At[mb * OROWW + kk * 8 + tig];
                af[mi][1] = At[(mb + 8) * OROWW + kk * 8 + tig];
                af[mi][2] = At[mb * OROWW + kk * 8 + tig + 4];
                af[mi][3] = At[(mb + 8) * OROWW + kk * 8 + tig + 4];
            }
            #pragma unroll
            for (int nj = 0; nj < 4; nj++) {
                int nb = wn + nj * 8 + g;
                bf[nj][0] = Bt[nb * OROWW + kk * 8 + tig];
                bf[nj][1] = Bt[nb * OROWW + kk * 8 + tig + 4];
            }
            #pragma unroll
            for (int mi = 0; mi < 4; mi++)
                #pragma unroll
                for (int nj = 0; nj < 4; nj++) mma16(acc[mi][nj], af[mi], bf[nj]);
        }
        int nk = kt + 2;
        if (nk < NC) {
            uint32_t st = sbase + (nk % 3) * O_STG_BYTES;
            const __nv_bfloat16* as = Ag + (size_t)lrow * HW + nk * 32 + lh * 16;
            const __nv_bfloat16* bs = Bg + (size_t)lrow * HW + nk * 32 + lh * 16;
            CPA16(st + lrow * 80 + lh * 32,              as);
            CPA16(st + lrow * 80 + lh * 32 + 16,         as + 8);
            CPA16(st + 10240 + lrow * 80 + lh * 32,      bs);
            CPA16(st + 10240 + lrow * 80 + lh * 32 + 16, bs + 8);
        }
        CPCOMMIT();
    }
    float* Cp = g_o + (size_t)b * HW * CCH;
    int m0 = blockIdx.x * 128, n0 = blockIdx.y * 128;
    #pragma unroll
    for (int mi = 0; mi < 4; mi++)
        #pragma unroll
        for (int nj = 0; nj < 4; nj++) {
            int r = m0 + wm + mi * 16 + g;
            int c = n0 + wn + nj * 8 + 2 * tig;
            *(float2*)&Cp[(size_t)r * CCH + c] =
                make_float2(acc[mi][nj][0], acc[mi][nj][1]);
            *(float2*)&Cp[(size_t)(r + 8) * CCH + c] =
                make_float2(acc[mi][nj][2], acc[mi][nj][3]);
        }
}

// ------ Proj+residual: out[o,m] = x[o,m] + sum_c O[m,c]Wp[o,c]+bp[o] ---------
__global__ __launch_bounds__(256, 2)
void proj_mma_kernel(const float* __restrict__ Wp, const float* __restrict__ bp,
                     const float* __restrict__ x, float* __restrict__ out) {
    extern __shared__ float smem[];
    int b = blockIdx.z;
    const float* Ag = g_o + (size_t)b * HW * CCH + (size_t)blockIdx.x * 128 * CCH;
    const float* xb = x   + (size_t)b * CCH * HW;
    float* ob = out + (size_t)b * CCH * HW;
    int n0 = blockIdx.y * 128, m0 = blockIdx.x * 128;
    int tid = threadIdx.x;
    int lane = tid & 31, warp = tid >> 5;
    int g = lane >> 2, tig = lane & 3;
    int wm = (warp >> 2) * 64, wn = (warp & 3) * 32;
    int brow = tid >> 2, bcol = (tid & 3) << 2;

    float acc[4][4][4];
    #pragma unroll
    for (int i = 0; i < 4; i++)
        #pragma unroll
        for (int j = 0; j < 4; j++)
            #pragma unroll
            for (int t = 0; t < 4; t++) acc[i][j][t] = 0.f;

    const int NT = CCH / 16;
    #pragma unroll
    for (int s = 0; s < 2; s++) {
        float* As = smem + s * SC_STG;
        float* Bs = As + 128 * PMK;
        #pragma unroll
        for (int rr = 0; rr < 2; rr++) {
            int r = brow + rr * 64;
            CPA16(sptr(&As[r * PMK + bcol]), Ag + (size_t)r * CCH + s * 16 + bcol);
            CPA16(sptr(&Bs[r * PMK + bcol]), Wp + (size_t)(n0 + r) * CCH + s * 16 + bcol);
        }
        CPCOMMIT();
    }
    for (int kt = 0; kt < NT; kt++) {
        CPWAIT1();
        __syncthreads();
        const float* Ab = smem + (kt % 3) * SC_STG;
        const float* Bb = Ab + 128 * PMK;
        unsigned af[4][4], bf[4][2];
        LOAD_AF_MK(af, Ab, 0, wm);
        LOAD_BF_MK(bf, Bb, 0, wn);
        MMA_ALL8(acc, af, bf);
        LOAD_AF_MK(af, Ab, 8, wm);
        LOAD_BF_MK(bf, Bb, 8, wn);
        MMA_ALL8(acc, af, bf);
        int nk = kt + 2;
        if (nk < NT) {
            float* As = smem + (nk % 3) * SC_STG;
            float* Bs = As + 128 * PMK;
            #pragma unroll
            for (int rr = 0; rr < 2; rr++) {
                int r = brow + rr * 64;
                CPA16(sptr(&As[r * PMK + bcol]), Ag + (size_t)r * CCH + nk * 16 + bcol);
                CPA16(sptr(&Bs[r * PMK + bcol]), Wp + (size_t)(n0 + r) * CCH + nk * 16 + bcol);
            }
        }
        CPCOMMIT();
    }
    #pragma unroll
    for (int nj = 0; nj < 4; nj++) {
        int c0 = n0 + wn + nj * 8 + 2 * tig;
        float bv0 = bp[c0], bv1 = bp[c0 + 1];
        #pragma unroll
        for (int mi = 0; mi < 4; mi++) {
            int r = m0 + wm + mi * 16 + g;
            ob[(size_t)c0 * HW + r]           = xb[(size_t)c0 * HW + r]           + acc[mi][nj][0] + bv0;
            ob[(size_t)(c0 + 1) * HW + r]     = xb[(size_t)(c0 + 1) * HW + r]     + acc[mi][nj][1] + bv1;
            ob[(size_t)c0 * HW + r + 8]       = xb[(size_t)c0 * HW + r + 8]       + acc[mi][nj][2] + bv0;
            ob[(size_t)(c0 + 1) * HW + r + 8] = xb[(size_t)(c0 + 1) * HW + r + 8] + acc[mi][nj][3] + bv1;
        }
    }
}

// ------------------------------ launch ---------------------------------------
extern "C" void kernel_launch(void* const* d_in, const int* in_sizes, int n_in,
                              void* d_out, int out_size) {
    const float* x  = (const float*)d_in[0];
    const float* nw = (const float*)d_in[1];
    const float* nb = (const float*)d_in[2];
    const float* wq = (const float*)d_in[3];
    const float* bq = (const float*)d_in[4];
    const float* wk = (const float*)d_in[5];
    const float* bk = (const float*)d_in[6];
    const float* wv = (const float*)d_in[7];
    const float* bv = (const float*)d_in[8];
    const float* wp = (const float*)d_in[9];
    const float* bp = (const float*)d_in[10];
    float* out = (float*)d_out;

    static int attr_done = 0;
    if (!attr_done) {
        cudaFuncSetAttribute(qkv_mma_kernel,
                             cudaFuncAttributeMaxDynamicSharedMemorySize, QKV_DYN);
        cudaFuncSetAttribute(scores_mma_kernel,
                             cudaFuncAttributeMaxDynamicSharedMemorySize, SC_DYN);
        cudaFuncSetAttribute(o_bf16_kernel,
                             cudaFuncAttributeMaxDynamicSharedMemorySize, O_DYN_B);
        cudaFuncSetAttribute(proj_mma_kernel,
                             cudaFuncAttributeMaxDynamicSharedMemorySize, SC_DYN);
        attr_done = 1;
    }

    groupnorm_kernel<<<BATCH * NGRP, 256>>>(x, nw, nb);

    dim3 gqkv(HW / 128, 3 * CCH / 128, BATCH);  // 32 x 12 x 2
    qkv_mma_kernel<<<gqkv, 256, QKV_DYN>>>(wq, bq, wk, bk, wv, bv);

    dim3 gsc(HW / 128, HW / 128, BATCH);        // 32 x 32 x 2
    scores_mma_kernel<<<gsc, 256, SC_DYN>>>();

    dim3 gzc(HW / 512, HW / ZROWBLK, BATCH);    // 8 x 64 x 2
    zcolsum_kernel<<<gzc, 256>>>();
    zfin_kernel<<<(BATCH * HW) / 256, 256>>>();
    vscale_kernel<<<(BATCH * CCH * HW) / (4 * 256), 256>>>();

    dim3 go(HW / 128, CCH / 128, BATCH);        // 32 x 4 x 2
    o_bf16_kernel<<<go, 256, O_DYN_B>>>();

    proj_mma_kernel<<<go, 256, SC_DYN>>>(wp, bp, x, out);
}

// round 11
// speedup vs baseline: 1.2183x; 1.2183x over previous
#include <cuda_runtime.h>
#include <cuda_bf16.h>
#include <math.h>
#include <float.h>
#include <stdint.h>

#define BATCH 2
#define CCH   512
#define HW    4096
#define NGRP  32
#define CPG   16
#define GRPELEM (CPG * HW)   // 65536

#define PMK 20    // padded row len for [row][k16] fp32 tiles (128 x 16)
#define PKM 136   // padded row len for [k16][col] fp32 tiles (16 x 128)

// per-stage float counts (tf32 kernels)
#define QKV_STG (16 * PKM + 128 * PMK)
#define SC_STG  (2 * 128 * PMK)
#define QKV_DYN (3 * QKV_STG * 4)
#define SC_DYN  (3 * SC_STG * 4)

// bf16 O GEMM geometry: k-chunk 32, rows padded to 20 words (40 bf16, 80 B)
#define OROWW 20
#define O_STG_WORDS (2 * 128 * OROWW)
#define O_STG_BYTES (O_STG_WORDS * 4)
#define O_DYN_B (3 * O_STG_BYTES)

#define ZROWBLK 64   // rows per zcolsum CTA

// ---------------- scratch (static device globals; no allocation) -------------
__device__ float         g_hn  [(size_t)BATCH * CCH * HW];  // normed [b][c][n]
__device__ float         g_q   [(size_t)BATCH * HW * CCH];  // [b][i][c]
__device__ float         g_k   [(size_t)BATCH * HW * CCH];  // [b][j][c]
__device__ float         g_vt  [(size_t)BATCH * CCH * HW];  // [b][c][i] fp32
__device__ __nv_bfloat16 g_vb  [(size_t)BATCH * CCH * HW];  // [b][c][i] bf16 * 1/Z_i
__device__ __nv_bfloat16 g_s   [(size_t)BATCH * HW * HW];   // E'[j][i] = exp(scale*S^T)
__device__ float         g_o   [(size_t)BATCH * HW * CCH];  // attn out [b][j][c]
__device__ float         g_zp  [(size_t)BATCH * (HW / ZROWBLK) * HW]; // partials
__device__ float         g_z   [(size_t)BATCH * HW];        // 1/Z_i

// ------------------------------ helpers --------------------------------------
__device__ __forceinline__ void mma8(float* d, const unsigned* a, const unsigned* b) {
    asm volatile(
        "mma.sync.aligned.m16n8k8.row.col.f32.tf32.tf32.f32 "
        "{%0,%1,%2,%3}, {%4,%5,%6,%7}, {%8,%9}, {%0,%1,%2,%3};\n"
        : "+f"(d[0]), "+f"(d[1]), "+f"(d[2]), "+f"(d[3])
        : "r"(a[0]), "r"(a[1]), "r"(a[2]), "r"(a[3]), "r"(b[0]), "r"(b[1]));
}
__device__ __forceinline__ void mma16(float* d, const unsigned* a, const unsigned* b) {
    asm volatile(
        "mma.sync.aligned.m16n8k16.row.col.f32.bf16.bf16.f32 "
        "{%0,%1,%2,%3}, {%4,%5,%6,%7}, {%8,%9}, {%0,%1,%2,%3};\n"
        : "+f"(d[0]), "+f"(d[1]), "+f"(d[2]), "+f"(d[3])
        : "r"(a[0]), "r"(a[1]), "r"(a[2]), "r"(a[3]), "r"(b[0]), "r"(b[1]));
}
__device__ __forceinline__ unsigned sptr(const void* p) {
    return (unsigned)__cvta_generic_to_shared(p);
}
#define CPA16(dst, src) asm volatile("cp.async.ca.shared.global [%0], [%1], 16;\n" :: "r"(dst), "l"(src))
#define CPCOMMIT()      asm volatile("cp.async.commit_group;\n")
#define CPWAIT1()       asm volatile("cp.async.wait_group 1;\n" ::: "memory")
__device__ __forceinline__ unsigned fu(float f) { return __float_as_uint(f); }

// ---------------------------- GroupNorm --------------------------------------
__global__ void groupnorm_kernel(const float* __restrict__ x,
                                 const float* __restrict__ gw,
                                 const float* __restrict__ gb) {
    int b = blockIdx.x >> 5;
    int g = blockIdx.x & 31;
    const float4* xp = (const float4*)(x    + ((size_t)b * CCH + g * CPG) * HW);
    float4*       op = (float4*)      (g_hn + ((size_t)b * CCH + g * CPG) * HW);
    int tid = threadIdx.x;

    float s = 0.f, ss = 0.f;
    for (int i = tid; i < GRPELEM / 4; i += 256) {
        float4 v = xp[i];
        s  += v.x + v.y + v.z + v.w;
        ss += v.x * v.x + v.y * v.y + v.z * v.z + v.w * v.w;
    }
    __shared__ float shs[8], shss[8];
    #pragma unroll
    for (int o = 16; o; o >>= 1) {
        s  += __shfl_xor_sync(0xffffffffu, s,  o);
        ss += __shfl_xor_sync(0xffffffffu, ss, o);
    }
    if ((tid & 31) == 0) { shs[tid >> 5] = s; shss[tid >> 5] = ss; }
    __syncthreads();
    __shared__ float sm, sr;
    if (tid == 0) {
        float S = 0.f, SS = 0.f;
        #pragma unroll
        for (int i = 0; i < 8; i++) { S += shs[i]; SS += shss[i]; }
        float mean = S / (float)GRPELEM;
        float var  = SS / (float)GRPELEM - mean * mean;
        sm = mean;
        sr = rsqrtf(var + 1e-6f);
    }
    __syncthreads();
    float mean = sm, rstd = sr;
    for (int i = tid; i < GRPELEM / 4; i += 256) {
        int cl = i >> 10;
        float sc = gw[g * CPG + cl] * rstd;
        float sh = gb[g * CPG + cl] - mean * sc;
        float4 v = xp[i];
        v.x = v.x * sc + sh; v.y = v.y * sc + sh;
        v.z = v.z * sc + sh; v.w = v.w * sc + sh;
        op[i] = v;
    }
}

// ---- frag loaders (fp32/tf32 tiles) -----------------------------------------
#define LOAD_AF_KM(af, Ab, kk, wm) do {                                        \
    _Pragma("unroll")                                                          \
    for (int mi = 0; mi < 4; mi++) {                                           \
        int mb = (wm) + mi * 16 + g;                                           \
        (af)[mi][0] = fu((Ab)[((kk) + tig) * PKM + mb]);                       \
        (af)[mi][1] = fu((Ab)[((kk) + tig) * PKM + mb + 8]);                   \
        (af)[mi][2] = fu((Ab)[((kk) + tig + 4) * PKM + mb]);                   \
        (af)[mi][3] = fu((Ab)[((kk) + tig + 4) * PKM + mb + 8]);               \
    } } while (0)
#define LOAD_AF_MK(af, Ab, kk, wm) do {                                        \
    _Pragma("unroll")                                                          \
    for (int mi = 0; mi < 4; mi++) {                                           \
        int mb = (wm) + mi * 16 + g;                                           \
        (af)[mi][0] = fu((Ab)[mb * PMK + (kk) + tig]);                         \
        (af)[mi][1] = fu((Ab)[(mb + 8) * PMK + (kk) + tig]);                   \
        (af)[mi][2] = fu((Ab)[mb * PMK + (kk) + tig + 4]);                     \
        (af)[mi][3] = fu((Ab)[(mb + 8) * PMK + (kk) + tig + 4]);               \
    } } while (0)
#define LOAD_BF_MK(bf, Bb, kk, wn) do {                                        \
    _Pragma("unroll")                                                          \
    for (int nj = 0; nj < 4; nj++) {                                           \
        int nb = (wn) + nj * 8 + g;                                            \
        (bf)[nj][0] = fu((Bb)[nb * PMK + (kk) + tig]);                         \
        (bf)[nj][1] = fu((Bb)[nb * PMK + (kk) + tig + 4]);                     \
    } } while (0)
#define MMA_ALL8(acc, af, bf) do {                                             \
    _Pragma("unroll")                                                          \
    for (int mi = 0; mi < 4; mi++)                                             \
        _Pragma("unroll")                                                      \
        for (int nj = 0; nj < 4; nj++) mma8((acc)[mi][nj], (af)[mi], (bf)[nj]);\
    } while (0)

// -------- QKV GEMM (merged): C[m,n] = sum_k A[k,m] * W[n,k] + bias[n] --------
__global__ __launch_bounds__(256, 2)
void qkv_mma_kernel(const float* __restrict__ wq, const float* __restrict__ bq,
                    const float* __restrict__ wk, const float* __restrict__ bk,
                    const float* __restrict__ wv, const float* __restrict__ bv) {
    extern __shared__ float smem[];
    int b = blockIdx.z;
    int which = blockIdx.y >> 2;
    int n0 = (blockIdx.y & 3) * 128, m0 = blockIdx.x * 128;
    const float* Wt   = which == 0 ? wq : which == 1 ? wk : wv;
    const float* bias = which == 0 ? bq : which == 1 ? bk : bv;
    const float* Ag = g_hn + (size_t)b * CCH * HW + m0;
    int tid = threadIdx.x;
    int lane = tid & 31, warp = tid >> 5;
    int g = lane >> 2, tig = lane & 3;
    int wm = (warp >> 2) * 64, wn = (warp & 3) * 32;
    int arow = tid >> 5, acol = (tid & 31) << 2;
    int brow = tid >> 2, bcol = (tid & 3) << 2;

    float acc[4][4][4];
    #pragma unroll
    for (int i = 0; i < 4; i++)
        #pragma unroll
        for (int j = 0; j < 4; j++)
            #pragma unroll
            for (int t = 0; t < 4; t++) acc[i][j][t] = 0.f;

    const int NT = CCH / 16;
    #pragma unroll
    for (int s = 0; s < 2; s++) {
        float* As = smem + s * QKV_STG;
        float* Bs = As + 16 * PKM;
        #pragma unroll
        for (int rr = 0; rr < 2; rr++) {
            int r = arow + rr * 8;
            CPA16(sptr(&As[r * PKM + acol]), Ag + (size_t)(s * 16 + r) * HW + acol);
        }
        #pragma unroll
        for (int rr = 0; rr < 2; rr++) {
            int r = brow + rr * 64;
            CPA16(sptr(&Bs[r * PMK + bcol]), Wt + (size_t)(n0 + r) * CCH + s * 16 + bcol);
        }
        CPCOMMIT();
    }
    for (int kt = 0; kt < NT; kt++) {
        CPWAIT1();
        __syncthreads();
        const float* Ab = smem + (kt % 3) * QKV_STG;
        const float* Bb = Ab + 16 * PKM;
        unsigned af[4][4], bf[4][2];
        LOAD_AF_KM(af, Ab, 0, wm);
        LOAD_BF_MK(bf, Bb, 0, wn);
        MMA_ALL8(acc, af, bf);
        LOAD_AF_KM(af, Ab, 8, wm);
        LOAD_BF_MK(bf, Bb, 8, wn);
        MMA_ALL8(acc, af, bf);
        int nk = kt + 2;
        if (nk < NT) {
            float* As = smem + (nk % 3) * QKV_STG;
            float* Bs = As + 16 * PKM;
            #pragma unroll
            for (int rr = 0; rr < 2; rr++) {
                int r = arow + rr * 8;
                CPA16(sptr(&As[r * PKM + acol]), Ag + (size_t)(nk * 16 + r) * HW + acol);
            }
            #pragma unroll
            for (int rr = 0; rr < 2; rr++) {
                int r = brow + rr * 64;
                CPA16(sptr(&Bs[r * PMK + bcol]), Wt + (size_t)(n0 + r) * CCH + nk * 16 + bcol);
            }
        }
        CPCOMMIT();
    }
    if (which == 2) {
        float* Vt = g_vt + (size_t)b * CCH * HW;
        #pragma unroll
        for (int mi = 0; mi < 4; mi++)
            #pragma unroll
            for (int nj = 0; nj < 4; nj++) {
                int r = m0 + wm + mi * 16 + g;
                int c = n0 + wn + nj * 8 + 2 * tig;
                float bv0 = bias[c], bv1 = bias[c + 1];
                Vt[(size_t)c * HW + r]           = acc[mi][nj][0] + bv0;
                Vt[(size_t)(c + 1) * HW + r]     = acc[mi][nj][1] + bv1;
                Vt[(size_t)c * HW + r + 8]       = acc[mi][nj][2] + bv0;
                Vt[(size_t)(c + 1) * HW + r + 8] = acc[mi][nj][3] + bv1;
            }
    } else {
        float* Cp = (which == 0 ? g_q : g_k) + (size_t)b * HW * CCH;
        #pragma unroll
        for (int mi = 0; mi < 4; mi++)
            #pragma unroll
            for (int nj = 0; nj < 4; nj++) {
                int r = m0 + wm + mi * 16 + g;
                int c = n0 + wn + nj * 8 + 2 * tig;
                float bv0 = bias[c], bv1 = bias[c + 1];
                *(float2*)&Cp[(size_t)r * CCH + c] =
                    make_float2(acc[mi][nj][0] + bv0, acc[mi][nj][1] + bv1);
                *(float2*)&Cp[(size_t)(r + 8) * CCH + c] =
                    make_float2(acc[mi][nj][2] + bv0, acc[mi][nj][3] + bv1);
            }
    }
}

// -------- Scores (transposed): E'[j,i] = exp(scale * K_j . Q_i) -> bf16 ------
__global__ __launch_bounds__(256, 2)
void scores_mma_kernel() {
    extern __shared__ float smem[];
    int b = blockIdx.z;
    const float* Ag = g_k + (size_t)b * HW * CCH + (size_t)blockIdx.x * 128 * CCH; // m = j
    const float* Bg = g_q + (size_t)b * HW * CCH + (size_t)blockIdx.y * 128 * CCH; // n = i
    int tid = threadIdx.x;
    int lane = tid & 31, warp = tid >> 5;
    int g = lane >> 2, tig = lane & 3;
    int wm = (warp >> 2) * 64, wn = (warp & 3) * 32;
    int brow = tid >> 2, bcol = (tid & 3) << 2;

    float acc[4][4][4];
    #pragma unroll
    for (int i = 0; i < 4; i++)
        #pragma unroll
        for (int j = 0; j < 4; j++)
            #pragma unroll
            for (int t = 0; t < 4; t++) acc[i][j][t] = 0.f;

    const int NT = CCH / 16;
    #pragma unroll
    for (int s = 0; s < 2; s++) {
        float* As = smem + s * SC_STG;
        float* Bs = As + 128 * PMK;
        #pragma unroll
        for (int rr = 0; rr < 2; rr++) {
            int r = brow + rr * 64;
            CPA16(sptr(&As[r * PMK + bcol]), Ag + (size_t)r * CCH + s * 16 + bcol);
            CPA16(sptr(&Bs[r * PMK + bcol]), Bg + (size_t)r * CCH + s * 16 + bcol);
        }
        CPCOMMIT();
    }
    for (int kt = 0; kt < NT; kt++) {
        CPWAIT1();
        __syncthreads();
        const float* Ab = smem + (kt % 3) * SC_STG;
        const float* Bb = Ab + 128 * PMK;
        unsigned af[4][4], bf[4][2];
        LOAD_AF_MK(af, Ab, 0, wm);
        LOAD_BF_MK(bf, Bb, 0, wn);
        MMA_ALL8(acc, af, bf);
        LOAD_AF_MK(af, Ab, 8, wm);
        LOAD_BF_MK(bf, Bb, 8, wn);
        MMA_ALL8(acc, af, bf);
        int nk = kt + 2;
        if (nk < NT) {
            float* As = smem + (nk % 3) * SC_STG;
            float* Bs = As + 128 * PMK;
            #pragma unroll
            for (int rr = 0; rr < 2; rr++) {
                int r = brow + rr * 64;
                CPA16(sptr(&As[r * PMK + bcol]), Ag + (size_t)r * CCH + nk * 16 + bcol);
                CPA16(sptr(&Bs[r * PMK + bcol]), Bg + (size_t)r * CCH + nk * 16 + bcol);
            }
        }
        CPCOMMIT();
    }
    const float scale = 0.04419417382415922f;   // 512^-0.5
    __nv_bfloat16* Cp = g_s + (size_t)b * HW * HW;
    int m0 = blockIdx.x * 128, n0 = blockIdx.y * 128;
    #pragma unroll
    for (int mi = 0; mi < 4; mi++)
        #pragma unroll
        for (int nj = 0; nj < 4; nj++) {
            int r = m0 + wm + mi * 16 + g;
            int c = n0 + wn + nj * 8 + 2 * tig;
            *(__nv_bfloat162*)&Cp[(size_t)r * HW + c] =
                __floats2bfloat162_rn(__expf(acc[mi][nj][0] * scale),
                                      __expf(acc[mi][nj][1] * scale));
            *(__nv_bfloat162*)&Cp[(size_t)(r + 8) * HW + c] =
                __floats2bfloat162_rn(__expf(acc[mi][nj][2] * scale),
                                      __expf(acc[mi][nj][3] * scale));
        }
}

// ------- column sums of E' stage 1: each CTA sums 64 rows x 512 cols ---------
__global__ void zcolsum_kernel() {
    int b = blockIdx.z;
    const __nv_bfloat162* S = (const __nv_bfloat162*)(g_s + (size_t)b * HW * HW);
    int t = threadIdx.x;
    size_t rowstride = HW / 2;
    const __nv_bfloat162* p = S + (size_t)(blockIdx.y * ZROWBLK) * rowstride
                                + blockIdx.x * 256 + t;
    float sx[8], sy[8];
    #pragma unroll
    for (int u = 0; u < 8; u++) { sx[u] = 0.f; sy[u] = 0.f; }
    #pragma unroll
    for (int jj = 0; jj < ZROWBLK / 8; jj++) {
        #pragma unroll
        for (int u = 0; u < 8; u++) {
            float2 v = __bfloat1622float2(p[(size_t)(jj * 8 + u) * rowstride]);
            sx[u] += v.x; sy[u] += v.y;
        }
    }
    float fx = (sx[0] + sx[1]) + (sx[2] + sx[3]) + ((sx[4] + sx[5]) + (sx[6] + sx[7]));
    float fy = (sy[0] + sy[1]) + (sy[2] + sy[3]) + ((sy[4] + sy[5]) + (sy[6] + sy[7]));
    float* zp = g_zp + ((size_t)(b * (HW / ZROWBLK) + blockIdx.y)) * HW
              + (size_t)(blockIdx.x * 256 + t) * 2;
    zp[0] = fx; zp[1] = fy;
}

// ------- stage 2: combine partials, reciprocal -------------------------------
__global__ void zfin_kernel() {
    int idx = blockIdx.x * 256 + threadIdx.x;   // < BATCH*HW
    int b = idx >> 12, i = idx & (HW - 1);
    const float* zp = g_zp + (size_t)b * (HW / ZROWBLK) * HW + i;
    float s0 = 0.f, s1 = 0.f, s2 = 0.f, s3 = 0.f;
    #pragma unroll
    for (int p = 0; p < HW / ZROWBLK; p += 4) {
        s0 += zp[(size_t)(p + 0) * HW];
        s1 += zp[(size_t)(p + 1) * HW];
        s2 += zp[(size_t)(p + 2) * HW];
        s3 += zp[(size_t)(p + 3) * HW];
    }
    g_z[idx] = 1.f / ((s0 + s1) + (s2 + s3));
}

// ------- V-hat: g_vb[c][i] = bf16(g_vt[c][i] * g_z[i]) -----------------------
__global__ void vscale_kernel() {
    size_t idx4 = (size_t)blockIdx.x * 256 + threadIdx.x;
    int b = (int)(idx4 / ((size_t)CCH * (HW / 4)));
    size_t rem = idx4 - (size_t)b * CCH * (HW / 4);
    int i4 = (int)(rem % (HW / 4));
    float4 v = ((const float4*)g_vt)[idx4];
    float4 z = ((const float4*)g_z)[(size_t)b * (HW / 4) + i4];
    __nv_bfloat162* o = ((__nv_bfloat162*)g_vb) + idx4 * 2;
    o[0] = __floats2bfloat162_rn(v.x * z.x, v.y * z.y);
    o[1] = __floats2bfloat162_rn(v.z * z.z, v.w * z.w);
}

// ------ O GEMM (bf16): O[j,c] = sum_i E'[j,i] * Vhat[c,i] --------------------
__global__ __launch_bounds__(256, 2)
void o_bf16_kernel() {
    extern __shared__ unsigned osm[];
    int b = blockIdx.z;
    const __nv_bfloat16* Ag = g_s  + (size_t)b * HW * HW + (size_t)(blockIdx.x * 128) * HW;
    const __nv_bfloat16* Bg = g_vb + (size_t)b * CCH * HW + (size_t)(blockIdx.y * 128) * HW;
    int tid = threadIdx.x;
    int lane = tid & 31, warp = tid >> 5;
    int g = lane >> 2, tig = lane & 3;
    int wm = (warp >> 2) * 64, wn = (warp & 3) * 32;
    int lrow = tid >> 1, lh = tid & 1;
    uint32_t sbase = sptr(osm);

    float acc[4][4][4];
    #pragma unroll
    for (int i = 0; i < 4; i++)
        #pragma unroll
        for (int j = 0; j < 4; j++)
            #pragma unroll
            for (int t = 0; t < 4; t++) acc[i][j][t] = 0.f;

    const int NC = HW / 32;
    #pragma unroll
    for (int s = 0; s < 2; s++) {
        uint32_t st = sbase + s * O_STG_BYTES;
        const __nv_bfloat16* as = Ag + (size_t)lrow * HW + s * 32 + lh * 16;
        const __nv_bfloat16* bs = Bg + (size_t)lrow * HW + s * 32 + lh * 16;
        CPA16(st + lrow * 80 + lh * 32,              as);
        CPA16(st + lrow * 80 + lh * 32 + 16,         as + 8);
        CPA16(st + 10240 + lrow * 80 + lh * 32,      bs);
        CPA16(st + 10240 + lrow * 80 + lh * 32 + 16, bs + 8);
        CPCOMMIT();
    }
    for (int kt = 0; kt < NC; kt++) {
        CPWAIT1();
        __syncthreads();
        const unsigned* At = osm + (kt % 3) * O_STG_WORDS;
        const unsigned* Bt = At + 128 * OROWW;
        #pragma unroll
        for (int kk = 0; kk < 2; kk++) {
            unsigned af[4][4], bf[4][2];
            #pragma unroll
            for (int mi = 0; mi < 4; mi++) {
                int mb = wm + mi * 16 + g;
                af[mi][0] = At[mb * OROWW + kk * 8 + tig];
                af[mi][1] = At[(mb + 8) * OROWW + kk * 8 + tig];
                af[mi][2] = At[mb * OROWW + kk * 8 + tig + 4];
                af[mi][3] = At[(mb + 8) * OROWW + kk * 8 + tig + 4];
            }
            #pragma unroll
            for (int nj = 0; nj < 4; nj++) {
                int nb = wn + nj * 8 + g;
                bf[nj][0] = Bt[nb * OROWW + kk * 8 + tig];
                bf[nj][1] = Bt[nb * OROWW + kk * 8 + tig + 4];
            }
            #pragma unroll
            for (int mi = 0; mi < 4; mi++)
                #pragma unroll
                for (int nj = 0; nj < 4; nj++) mma16(acc[mi][nj], af[mi], bf[nj]);
        }
        int nk = kt + 2;
        if (nk < NC) {
            uint32_t st = sbase + (nk % 3) * O_STG_BYTES;
            const __nv_bfloat16* as = Ag + (size_t)lrow * HW + nk * 32 + lh * 16;
            const __nv_bfloat16* bs = Bg + (size_t)lrow * HW + nk * 32 + lh * 16;
            CPA16(st + lrow * 80 + lh * 32,              as);
            CPA16(st + lrow * 80 + lh * 32 + 16,         as + 8);
            CPA16(st + 10240 + lrow * 80 + lh * 32,      bs);
            CPA16(st + 10240 + lrow * 80 + lh * 32 + 16, bs + 8);
        }
        CPCOMMIT();
    }
    float* Cp = g_o + (size_t)b * HW * CCH;
    int m0 = blockIdx.x * 128, n0 = blockIdx.y * 128;
    #pragma unroll
    for (int mi = 0; mi < 4; mi++)
        #pragma unroll
        for (int nj = 0; nj < 4; nj++) {
            int r = m0 + wm + mi * 16 + g;
            int c = n0 + wn + nj * 8 + 2 * tig;
            *(float2*)&Cp[(size_t)r * CCH + c] =
                make_float2(acc[mi][nj][0], acc[mi][nj][1]);
            *(float2*)&Cp[(size_t)(r + 8) * CCH + c] =
                make_float2(acc[mi][nj][2], acc[mi][nj][3]);
        }
}

// ------ Proj+residual: out[o,m] = x[o,m] + sum_c O[m,c]Wp[o,c]+bp[o] ---------
__global__ __launch_bounds__(256, 2)
void proj_mma_kernel(const float* __restrict__ Wp, const float* __restrict__ bp,
                     const float* __restrict__ x, float* __restrict__ out) {
    extern __shared__ float smem[];
    int b = blockIdx.z;
    const float* Ag = g_o + (size_t)b * HW * CCH + (size_t)blockIdx.x * 128 * CCH;
    const float* xb = x   + (size_t)b * CCH * HW;
    float* ob = out + (size_t)b * CCH * HW;
    int n0 = blockIdx.y * 128, m0 = blockIdx.x * 128;
    int tid = threadIdx.x;
    int lane = tid & 31, warp = tid >> 5;
    int g = lane >> 2, tig = lane & 3;
    int wm = (warp >> 2) * 64, wn = (warp & 3) * 32;
    int brow = tid >> 2, bcol = (tid & 3) << 2;

    float acc[4][4][4];
    #pragma unroll
    for (int i = 0; i < 4; i++)
        #pragma unroll
        for (int j = 0; j < 4; j++)
            #pragma unroll
            for (int t = 0; t < 4; t++) acc[i][j][t] = 0.f;

    const int NT = CCH / 16;
    #pragma unroll
    for (int s = 0; s < 2; s++) {
        float* As = smem + s * SC_STG;
        float* Bs = As + 128 * PMK;
        #pragma unroll
        for (int rr = 0; rr < 2; rr++) {
            int r = brow + rr * 64;
            CPA16(sptr(&As[r * PMK + bcol]), Ag + (size_t)r * CCH + s * 16 + bcol);
            CPA16(sptr(&Bs[r * PMK + bcol]), Wp + (size_t)(n0 + r) * CCH + s * 16 + bcol);
        }
        CPCOMMIT();
    }
    for (int kt = 0; kt < NT; kt++) {
        CPWAIT1();
        __syncthreads();
        const float* Ab = smem + (kt % 3) * SC_STG;
        const float* Bb = Ab + 128 * PMK;
        unsigned af[4][4], bf[4][2];
        LOAD_AF_MK(af, Ab, 0, wm);
        LOAD_BF_MK(bf, Bb, 0, wn);
        MMA_ALL8(acc, af, bf);
        LOAD_AF_MK(af, Ab, 8, wm);
        LOAD_BF_MK(bf, Bb, 8, wn);
        MMA_ALL8(acc, af, bf);
        int nk = kt + 2;
        if (nk < NT) {
            float* As = smem + (nk % 3) * SC_STG;
            float* Bs = As + 128 * PMK;
            #pragma unroll
            for (int rr = 0; rr < 2; rr++) {
                int r = brow + rr * 64;
                CPA16(sptr(&As[r * PMK + bcol]), Ag + (size_t)r * CCH + nk * 16 + bcol);
                CPA16(sptr(&Bs[r * PMK + bcol]), Wp + (size_t)(n0 + r) * CCH + nk * 16 + bcol);
            }
        }
        CPCOMMIT();
    }
    #pragma unroll
    for (int nj = 0; nj < 4; nj++) {
        int c0 = n0 + wn + nj * 8 + 2 * tig;
        float bv0 = bp[c0], bv1 = bp[c0 + 1];
        #pragma unroll
        for (int mi = 0; mi < 4; mi++) {
            int r = m0 + wm + mi * 16 + g;
            ob[(size_t)c0 * HW + r]           = xb[(size_t)c0 * HW + r]           + acc[mi][nj][0] + bv0;
            ob[(size_t)(c0 + 1) * HW + r]     = xb[(size_t)(c0 + 1) * HW + r]     + acc[mi][nj][1] + bv1;
            ob[(size_t)c0 * HW + r + 8]       = xb[(size_t)c0 * HW + r + 8]       + acc[mi][nj][2] + bv0;
            ob[(size_t)(c0 + 1) * HW + r + 8] = xb[(size_t)(c0 + 1) * HW + r + 8] + acc[mi][nj][3] + bv1;
        }
    }
}

// ------------------------------ launch ---------------------------------------
extern "C" void kernel_launch(void* const* d_in, const int* in_sizes, int n_in,
                              void* d_out, int out_size) {
    const float* x  = (const float*)d_in[0];
    const float* nw = (const float*)d_in[1];
    const float* nb = (const float*)d_in[2];
    const float* wq = (const float*)d_in[3];
    const float* bq = (const float*)d_in[4];
    const float* wk = (const float*)d_in[5];
    const float* bk = (const float*)d_in[6];
    const float* wv = (const float*)d_in[7];
    const float* bv = (const float*)d_in[8];
    const float* wp = (const float*)d_in[9];
    const float* bp = (const float*)d_in[10];
    float* out = (float*)d_out;

    static int attr_done = 0;
    if (!attr_done) {
        cudaFuncSetAttribute(qkv_mma_kernel,
                             cudaFuncAttributeMaxDynamicSharedMemorySize, QKV_DYN);
        cudaFuncSetAttribute(scores_mma_kernel,
                             cudaFuncAttributeMaxDynamicSharedMemorySize, SC_DYN);
        cudaFuncSetAttribute(o_bf16_kernel,
                             cudaFuncAttributeMaxDynamicSharedMemorySize, O_DYN_B);
        cudaFuncSetAttribute(proj_mma_kernel,
                             cudaFuncAttributeMaxDynamicSharedMemorySize, SC_DYN);
        attr_done = 1;
    }

    groupnorm_kernel<<<BATCH * NGRP, 256>>>(x, nw, nb);

    dim3 gqkv(HW / 128, 3 * CCH / 128, BATCH);  // 32 x 12 x 2
    qkv_mma_kernel<<<gqkv, 256, QKV_DYN>>>(wq, bq, wk, bk, wv, bv);

    dim3 gsc(HW / 128, HW / 128, BATCH);        // 32 x 32 x 2
    scores_mma_kernel<<<gsc, 256, SC_DYN>>>();

    dim3 gzc(HW / 512, HW / ZROWBLK, BATCH);    // 8 x 64 x 2
    zcolsum_kernel<<<gzc, 256>>>();
    zfin_kernel<<<(BATCH * HW) / 256, 256>>>();
    vscale_kernel<<<(BATCH * CCH * HW) / (4 * 256), 256>>>();

    dim3 go(HW / 128, CCH / 128, BATCH);        // 32 x 4 x 2
    o_bf16_kernel<<<go, 256, O_DYN_B>>>();

    proj_mma_kernel<<<go, 256, SC_DYN>>>(wp, bp, x, out);
}

// round 12
// speedup vs baseline: 1.4597x; 1.1982x over previous
#include <cuda_runtime.h>
#include <cuda_bf16.h>
#include <math.h>
#include <float.h>
#include <stdint.h>

#define BATCH 2
#define CCH   512
#define HW    4096
#define NGRP  32
#define CPG   16
#define GRPELEM (CPG * HW)   // 65536

#define PMK 20    // padded row len for [row][k16] fp32 tiles (128 x 16)
#define PKM 136   // padded row len for [k16][col] fp32 tiles (16 x 128)

// per-stage float counts (tf32 kernels)
#define QKV_STG (16 * PKM + 128 * PMK)
#define SC_STG  (2 * 128 * PMK)
#define QKV_DYN (3 * QKV_STG * 4)
#define SC_DYN  (3 * SC_STG * 4)

// bf16 GEMM geometry: k-chunk 32, rows padded to 20 words (40 bf16, 80 B)
#define OROWW 20
#define O_STG_WORDS (2 * 128 * OROWW)
#define O_STG_BYTES (O_STG_WORDS * 4)
#define O_DYN_B (3 * O_STG_BYTES)

#define ZROWBLK 64   // rows per zcolsum CTA

// ---------------- scratch (static device globals; no allocation) -------------
__device__ float         g_hn  [(size_t)BATCH * CCH * HW];  // normed [b][c][n]
__device__ __nv_bfloat16 g_q   [(size_t)BATCH * HW * CCH];  // [b][i][c] bf16
__device__ __nv_bfloat16 g_k   [(size_t)BATCH * HW * CCH];  // [b][j][c] bf16
__device__ float         g_vt  [(size_t)BATCH * CCH * HW];  // [b][c][i] fp32
__device__ __nv_bfloat16 g_vb  [(size_t)BATCH * CCH * HW];  // [b][c][i] bf16 * 1/Z_i
__device__ __nv_bfloat16 g_s   [(size_t)BATCH * HW * HW];   // E'[j][i] = exp(scale*S^T)
__device__ float         g_o   [(size_t)BATCH * HW * CCH];  // attn out [b][j][c]
__device__ float         g_zp  [(size_t)BATCH * (HW / ZROWBLK) * HW]; // partials
__device__ float         g_z   [(size_t)BATCH * HW];        // 1/Z_i

// ------------------------------ helpers --------------------------------------
__device__ __forceinline__ void mma8(float* d, const unsigned* a, const unsigned* b) {
    asm volatile(
        "mma.sync.aligned.m16n8k8.row.col.f32.tf32.tf32.f32 "
        "{%0,%1,%2,%3}, {%4,%5,%6,%7}, {%8,%9}, {%0,%1,%2,%3};\n"
        : "+f"(d[0]), "+f"(d[1]), "+f"(d[2]), "+f"(d[3])
        : "r"(a[0]), "r"(a[1]), "r"(a[2]), "r"(a[3]), "r"(b[0]), "r"(b[1]));
}
__device__ __forceinline__ void mma16(float* d, const unsigned* a, const unsigned* b) {
    asm volatile(
        "mma.sync.aligned.m16n8k16.row.col.f32.bf16.bf16.f32 "
        "{%0,%1,%2,%3}, {%4,%5,%6,%7}, {%8,%9}, {%0,%1,%2,%3};\n"
        : "+f"(d[0]), "+f"(d[1]), "+f"(d[2]), "+f"(d[3])
        : "r"(a[0]), "r"(a[1]), "r"(a[2]), "r"(a[3]), "r"(b[0]), "r"(b[1]));
}
__device__ __forceinline__ unsigned sptr(const void* p) {
    return (unsigned)__cvta_generic_to_shared(p);
}
#define CPA16(dst, src) asm volatile("cp.async.ca.shared.global [%0], [%1], 16;\n" :: "r"(dst), "l"(src))
#define CPCOMMIT()      asm volatile("cp.async.commit_group;\n")
#define CPWAIT1()       asm volatile("cp.async.wait_group 1;\n" ::: "memory")
__device__ __forceinline__ unsigned fu(float f) { return __float_as_uint(f); }

// ---------------------------- GroupNorm --------------------------------------
__global__ void groupnorm_kernel(const float* __restrict__ x,
                                 const float* __restrict__ gw,
                                 const float* __restrict__ gb) {
    int b = blockIdx.x >> 5;
    int g = blockIdx.x & 31;
    const float4* xp = (const float4*)(x    + ((size_t)b * CCH + g * CPG) * HW);
    float4*       op = (float4*)      (g_hn + ((size_t)b * CCH + g * CPG) * HW);
    int tid = threadIdx.x;

    float s = 0.f, ss = 0.f;
    for (int i = tid; i < GRPELEM / 4; i += 256) {
        float4 v = xp[i];
        s  += v.x + v.y + v.z + v.w;
        ss += v.x * v.x + v.y * v.y + v.z * v.z + v.w * v.w;
    }
    __shared__ float shs[8], shss[8];
    #pragma unroll
    for (int o = 16; o; o >>= 1) {
        s  += __shfl_xor_sync(0xffffffffu, s,  o);
        ss += __shfl_xor_sync(0xffffffffu, ss, o);
    }
    if ((tid & 31) == 0) { shs[tid >> 5] = s; shss[tid >> 5] = ss; }
    __syncthreads();
    __shared__ float sm, sr;
    if (tid == 0) {
        float S = 0.f, SS = 0.f;
        #pragma unroll
        for (int i = 0; i < 8; i++) { S += shs[i]; SS += shss[i]; }
        float mean = S / (float)GRPELEM;
        float var  = SS / (float)GRPELEM - mean * mean;
        sm = mean;
        sr = rsqrtf(var + 1e-6f);
    }
    __syncthreads();
    float mean = sm, rstd = sr;
    for (int i = tid; i < GRPELEM / 4; i += 256) {
        int cl = i >> 10;
        float sc = gw[g * CPG + cl] * rstd;
        float sh = gb[g * CPG + cl] - mean * sc;
        float4 v = xp[i];
        v.x = v.x * sc + sh; v.y = v.y * sc + sh;
        v.z = v.z * sc + sh; v.w = v.w * sc + sh;
        op[i] = v;
    }
}

// ---- frag loaders (fp32/tf32 tiles) -----------------------------------------
#define LOAD_AF_KM(af, Ab, kk, wm) do {                                        \
    _Pragma("unroll")                                                          \
    for (int mi = 0; mi < 4; mi++) {                                           \
        int mb = (wm) + mi * 16 + g;                                           \
        (af)[mi][0] = fu((Ab)[((kk) + tig) * PKM + mb]);                       \
        (af)[mi][1] = fu((Ab)[((kk) + tig) * PKM + mb + 8]);                   \
        (af)[mi][2] = fu((Ab)[((kk) + tig + 4) * PKM + mb]);                   \
        (af)[mi][3] = fu((Ab)[((kk) + tig + 4) * PKM + mb + 8]);               \
    } } while (0)
#define LOAD_AF_MK(af, Ab, kk, wm) do {                                        \
    _Pragma("unroll")                                                          \
    for (int mi = 0; mi < 4; mi++) {                                           \
        int mb = (wm) + mi * 16 + g;                                           \
        (af)[mi][0] = fu((Ab)[mb * PMK + (kk) + tig]);                         \
        (af)[mi][1] = fu((Ab)[(mb + 8) * PMK + (kk) + tig]);                   \
        (af)[mi][2] = fu((Ab)[mb * PMK + (kk) + tig + 4]);                     \
        (af)[mi][3] = fu((Ab)[(mb + 8) * PMK + (kk) + tig + 4]);               \
    } } while (0)
#define LOAD_BF_MK(bf, Bb, kk, wn) do {                                        \
    _Pragma("unroll")                                                          \
    for (int nj = 0; nj < 4; nj++) {                                           \
        int nb = (wn) + nj * 8 + g;                                            \
        (bf)[nj][0] = fu((Bb)[nb * PMK + (kk) + tig]);                         \
        (bf)[nj][1] = fu((Bb)[nb * PMK + (kk) + tig + 4]);                     \
    } } while (0)
#define MMA_ALL8(acc, af, bf) do {                                             \
    _Pragma("unroll")                                                          \
    for (int mi = 0; mi < 4; mi++)                                             \
        _Pragma("unroll")                                                      \
        for (int nj = 0; nj < 4; nj++) mma8((acc)[mi][nj], (af)[mi], (bf)[nj]);\
    } while (0)

// ---- bf16 MK-tile mainloop body (both operands [128 rows][32 bf16], 80B pitch)
#define BF16_CHUNK_MMAS(acc, At, Bt)  do {                                     \
    _Pragma("unroll")                                                          \
    for (int kk = 0; kk < 2; kk++) {                                           \
        unsigned af[4][4], bf[4][2];                                           \
        _Pragma("unroll")                                                      \
        for (int mi = 0; mi < 4; mi++) {                                       \
            int mb = wm + mi * 16 + g;                                         \
            af[mi][0] = (At)[mb * OROWW + kk * 8 + tig];                       \
            af[mi][1] = (At)[(mb + 8) * OROWW + kk * 8 + tig];                 \
            af[mi][2] = (At)[mb * OROWW + kk * 8 + tig + 4];                   \
            af[mi][3] = (At)[(mb + 8) * OROWW + kk * 8 + tig + 4];             \
        }                                                                      \
        _Pragma("unroll")                                                      \
        for (int nj = 0; nj < 4; nj++) {                                       \
            int nb = wn + nj * 8 + g;                                          \
            bf[nj][0] = (Bt)[nb * OROWW + kk * 8 + tig];                       \
            bf[nj][1] = (Bt)[nb * OROWW + kk * 8 + tig + 4];                   \
        }                                                                      \
        _Pragma("unroll")                                                      \
        for (int mi = 0; mi < 4; mi++)                                         \
            _Pragma("unroll")                                                  \
            for (int nj = 0; nj < 4; nj++) mma16((acc)[mi][nj], af[mi], bf[nj]); \
    } } while (0)

#define BF16_LOAD_STAGE(st, Ag, Astr, Bg, Bstr, ck) do {                       \
    const __nv_bfloat16* as = (Ag) + (size_t)lrow * (Astr) + (ck) * 32 + lh * 16; \
    const __nv_bfloat16* bs = (Bg) + (size_t)lrow * (Bstr) + (ck) * 32 + lh * 16; \
    CPA16((st) + lrow * 80 + lh * 32,              as);                        \
    CPA16((st) + lrow * 80 + lh * 32 + 16,         as + 8);                    \
    CPA16((st) + 10240 + lrow * 80 + lh * 32,      bs);                        \
    CPA16((st) + 10240 + lrow * 80 + lh * 32 + 16, bs + 8);                    \
    } while (0)

// -------- QKV GEMM (merged): C[m,n] = sum_k A[k,m] * W[n,k] + bias[n] --------
// which 0 -> g_q bf16 [i][c], 1 -> g_k bf16 [j][c], 2 -> g_vt fp32 [c][i]
__global__ __launch_bounds__(256, 2)
void qkv_mma_kernel(const float* __restrict__ wq, const float* __restrict__ bq,
                    const float* __restrict__ wk, const float* __restrict__ bk,
                    const float* __restrict__ wv, const float* __restrict__ bv) {
    extern __shared__ float smem[];
    int b = blockIdx.z;
    int which = blockIdx.y >> 2;
    int n0 = (blockIdx.y & 3) * 128, m0 = blockIdx.x * 128;
    const float* Wt   = which == 0 ? wq : which == 1 ? wk : wv;
    const float* bias = which == 0 ? bq : which == 1 ? bk : bv;
    const float* Ag = g_hn + (size_t)b * CCH * HW + m0;
    int tid = threadIdx.x;
    int lane = tid & 31, warp = tid >> 5;
    int g = lane >> 2, tig = lane & 3;
    int wm = (warp >> 2) * 64, wn = (warp & 3) * 32;
    int arow = tid >> 5, acol = (tid & 31) << 2;
    int brow = tid >> 2, bcol = (tid & 3) << 2;

    float acc[4][4][4];
    #pragma unroll
    for (int i = 0; i < 4; i++)
        #pragma unroll
        for (int j = 0; j < 4; j++)
            #pragma unroll
            for (int t = 0; t < 4; t++) acc[i][j][t] = 0.f;

    const int NT = CCH / 16;
    #pragma unroll
    for (int s = 0; s < 2; s++) {
        float* As = smem + s * QKV_STG;
        float* Bs = As + 16 * PKM;
        #pragma unroll
        for (int rr = 0; rr < 2; rr++) {
            int r = arow + rr * 8;
            CPA16(sptr(&As[r * PKM + acol]), Ag + (size_t)(s * 16 + r) * HW + acol);
        }
        #pragma unroll
        for (int rr = 0; rr < 2; rr++) {
            int r = brow + rr * 64;
            CPA16(sptr(&Bs[r * PMK + bcol]), Wt + (size_t)(n0 + r) * CCH + s * 16 + bcol);
        }
        CPCOMMIT();
    }
    for (int kt = 0; kt < NT; kt++) {
        CPWAIT1();
        __syncthreads();
        const float* Ab = smem + (kt % 3) * QKV_STG;
        const float* Bb = Ab + 16 * PKM;
        unsigned af[4][4], bf[4][2];
        LOAD_AF_KM(af, Ab, 0, wm);
        LOAD_BF_MK(bf, Bb, 0, wn);
        MMA_ALL8(acc, af, bf);
        LOAD_AF_KM(af, Ab, 8, wm);
        LOAD_BF_MK(bf, Bb, 8, wn);
        MMA_ALL8(acc, af, bf);
        int nk = kt + 2;
        if (nk < NT) {
            float* As = smem + (nk % 3) * QKV_STG;
            float* Bs = As + 16 * PKM;
            #pragma unroll
            for (int rr = 0; rr < 2; rr++) {
                int r = arow + rr * 8;
                CPA16(sptr(&As[r * PKM + acol]), Ag + (size_t)(nk * 16 + r) * HW + acol);
            }
            #pragma unroll
            for (int rr = 0; rr < 2; rr++) {
                int r = brow + rr * 64;
                CPA16(sptr(&Bs[r * PMK + bcol]), Wt + (size_t)(n0 + r) * CCH + nk * 16 + bcol);
            }
        }
        CPCOMMIT();
    }
    if (which == 2) {
        float* Vt = g_vt + (size_t)b * CCH * HW;
        #pragma unroll
        for (int mi = 0; mi < 4; mi++)
            #pragma unroll
            for (int nj = 0; nj < 4; nj++) {
                int r = m0 + wm + mi * 16 + g;
                int c = n0 + wn + nj * 8 + 2 * tig;
                float bv0 = bias[c], bv1 = bias[c + 1];
                Vt[(size_t)c * HW + r]           = acc[mi][nj][0] + bv0;
                Vt[(size_t)(c + 1) * HW + r]     = acc[mi][nj][1] + bv1;
                Vt[(size_t)c * HW + r + 8]       = acc[mi][nj][2] + bv0;
                Vt[(size_t)(c + 1) * HW + r + 8] = acc[mi][nj][3] + bv1;
            }
    } else {
        __nv_bfloat16* Cp = (which == 0 ? g_q : g_k) + (size_t)b * HW * CCH;
        #pragma unroll
        for (int mi = 0; mi < 4; mi++)
            #pragma unroll
            for (int nj = 0; nj < 4; nj++) {
                int r = m0 + wm + mi * 16 + g;
                int c = n0 + wn + nj * 8 + 2 * tig;
                float bv0 = bias[c], bv1 = bias[c + 1];
                *(__nv_bfloat162*)&Cp[(size_t)r * CCH + c] =
                    __floats2bfloat162_rn(acc[mi][nj][0] + bv0, acc[mi][nj][1] + bv1);
                *(__nv_bfloat162*)&Cp[(size_t)(r + 8) * CCH + c] =
                    __floats2bfloat162_rn(acc[mi][nj][2] + bv0, acc[mi][nj][3] + bv1);
            }
    }
}

// -------- Scores (bf16): E'[j,i] = exp(scale * K_j . Q_i) -> bf16 ------------
__global__ __launch_bounds__(256, 2)
void scores_bf16_kernel() {
    extern __shared__ unsigned ssm[];
    int b = blockIdx.z;
    const __nv_bfloat16* Ag = g_k + (size_t)b * HW * CCH + (size_t)(blockIdx.x * 128) * CCH;
    const __nv_bfloat16* Bg = g_q + (size_t)b * HW * CCH + (size_t)(blockIdx.y * 128) * CCH;
    int tid = threadIdx.x;
    int lane = tid & 31, warp = tid >> 5;
    int g = lane >> 2, tig = lane & 3;
    int wm = (warp >> 2) * 64, wn = (warp & 3) * 32;
    int lrow = tid >> 1, lh = tid & 1;
    uint32_t sbase = sptr(ssm);

    float acc[4][4][4];
    #pragma unroll
    for (int i = 0; i < 4; i++)
        #pragma unroll
        for (int j = 0; j < 4; j++)
            #pragma unroll
            for (int t = 0; t < 4; t++) acc[i][j][t] = 0.f;

    const int NC = CCH / 32;   // 16
    #pragma unroll
    for (int s = 0; s < 2; s++) {
        BF16_LOAD_STAGE(sbase + s * O_STG_BYTES, Ag, CCH, Bg, CCH, s);
        CPCOMMIT();
    }
    for (int kt = 0; kt < NC; kt++) {
        CPWAIT1();
        __syncthreads();
        const unsigned* At = ssm + (kt % 3) * O_STG_WORDS;
        const unsigned* Bt = At + 128 * OROWW;
        BF16_CHUNK_MMAS(acc, At, Bt);
        int nk = kt + 2;
        if (nk < NC) {
            BF16_LOAD_STAGE(sbase + (nk % 3) * O_STG_BYTES, Ag, CCH, Bg, CCH, nk);
        }
        CPCOMMIT();
    }
    const float scale = 0.04419417382415922f;   // 512^-0.5
    __nv_bfloat16* Cp = g_s + (size_t)b * HW * HW;
    int m0 = blockIdx.x * 128, n0 = blockIdx.y * 128;
    #pragma unroll
    for (int mi = 0; mi < 4; mi++)
        #pragma unroll
        for (int nj = 0; nj < 4; nj++) {
            int r = m0 + wm + mi * 16 + g;
            int c = n0 + wn + nj * 8 + 2 * tig;
            *(__nv_bfloat162*)&Cp[(size_t)r * HW + c] =
                __floats2bfloat162_rn(__expf(acc[mi][nj][0] * scale),
                                      __expf(acc[mi][nj][1] * scale));
            *(__nv_bfloat162*)&Cp[(size_t)(r + 8) * HW + c] =
                __floats2bfloat162_rn(__expf(acc[mi][nj][2] * scale),
                                      __expf(acc[mi][nj][3] * scale));
        }
}

// ------- column sums of E' stage 1: each CTA sums 64 rows x 512 cols ---------
__global__ void zcolsum_kernel() {
    int b = blockIdx.z;
    const __nv_bfloat162* S = (const __nv_bfloat162*)(g_s + (size_t)b * HW * HW);
    int t = threadIdx.x;
    size_t rowstride = HW / 2;
    const __nv_bfloat162* p = S + (size_t)(blockIdx.y * ZROWBLK) * rowstride
                                + blockIdx.x * 256 + t;
    float sx[8], sy[8];
    #pragma unroll
    for (int u = 0; u < 8; u++) { sx[u] = 0.f; sy[u] = 0.f; }
    #pragma unroll
    for (int jj = 0; jj < ZROWBLK / 8; jj++) {
        #pragma unroll
        for (int u = 0; u < 8; u++) {
            float2 v = __bfloat1622float2(p[(size_t)(jj * 8 + u) * rowstride]);
            sx[u] += v.x; sy[u] += v.y;
        }
    }
    float fx = (sx[0] + sx[1]) + (sx[2] + sx[3]) + ((sx[4] + sx[5]) + (sx[6] + sx[7]));
    float fy = (sy[0] + sy[1]) + (sy[2] + sy[3]) + ((sy[4] + sy[5]) + (sy[6] + sy[7]));
    float* zp = g_zp + ((size_t)(b * (HW / ZROWBLK) + blockIdx.y)) * HW
              + (size_t)(blockIdx.x * 256 + t) * 2;
    zp[0] = fx; zp[1] = fy;
}

// ------- stage 2: combine partials, reciprocal -------------------------------
__global__ void zfin_kernel() {
    int idx = blockIdx.x * 256 + threadIdx.x;   // < BATCH*HW
    int b = idx >> 12, i = idx & (HW - 1);
    const float* zp = g_zp + (size_t)b * (HW / ZROWBLK) * HW + i;
    float s0 = 0.f, s1 = 0.f, s2 = 0.f, s3 = 0.f;
    #pragma unroll
    for (int p = 0; p < HW / ZROWBLK; p += 4) {
        s0 += zp[(size_t)(p + 0) * HW];
        s1 += zp[(size_t)(p + 1) * HW];
        s2 += zp[(size_t)(p + 2) * HW];
        s3 += zp[(size_t)(p + 3) * HW];
    }
    g_z[idx] = 1.f / ((s0 + s1) + (s2 + s3));
}

// ------- V-hat: g_vb[c][i] = bf16(g_vt[c][i] * g_z[i]) -----------------------
__global__ void vscale_kernel() {
    size_t idx4 = (size_t)blockIdx.x * 256 + threadIdx.x;
    int b = (int)(idx4 / ((size_t)CCH * (HW / 4)));
    size_t rem = idx4 - (size_t)b * CCH * (HW / 4);
    int i4 = (int)(rem % (HW / 4));
    float4 v = ((const float4*)g_vt)[idx4];
    float4 z = ((const float4*)g_z)[(size_t)b * (HW / 4) + i4];
    __nv_bfloat162* o = ((__nv_bfloat162*)g_vb) + idx4 * 2;
    o[0] = __floats2bfloat162_rn(v.x * z.x, v.y * z.y);
    o[1] = __floats2bfloat162_rn(v.z * z.z, v.w * z.w);
}

// ------ O GEMM (bf16): O[j,c] = sum_i E'[j,i] * Vhat[c,i] --------------------
__global__ __launch_bounds__(256, 2)
void o_bf16_kernel() {
    extern __shared__ unsigned osm[];
    int b = blockIdx.z;
    const __nv_bfloat16* Ag = g_s  + (size_t)b * HW * HW + (size_t)(blockIdx.x * 128) * HW;
    const __nv_bfloat16* Bg = g_vb + (size_t)b * CCH * HW + (size_t)(blockIdx.y * 128) * HW;
    int tid = threadIdx.x;
    int lane = tid & 31, warp = tid >> 5;
    int g = lane >> 2, tig = lane & 3;
    int wm = (warp >> 2) * 64, wn = (warp & 3) * 32;
    int lrow = tid >> 1, lh = tid & 1;
    uint32_t sbase = sptr(osm);

    float acc[4][4][4];
    #pragma unroll
    for (int i = 0; i < 4; i++)
        #pragma unroll
        for (int j = 0; j < 4; j++)
            #pragma unroll
            for (int t = 0; t < 4; t++) acc[i][j][t] = 0.f;

    const int NC = HW / 32;
    #pragma unroll
    for (int s = 0; s < 2; s++) {
        BF16_LOAD_STAGE(sbase + s * O_STG_BYTES, Ag, HW, Bg, HW, s);
        CPCOMMIT();
    }
    for (int kt = 0; kt < NC; kt++) {
        CPWAIT1();
        __syncthreads();
        const unsigned* At = osm + (kt % 3) * O_STG_WORDS;
        const unsigned* Bt = At + 128 * OROWW;
        BF16_CHUNK_MMAS(acc, At, Bt);
        int nk = kt + 2;
        if (nk < NC) {
            BF16_LOAD_STAGE(sbase + (nk % 3) * O_STG_BYTES, Ag, HW, Bg, HW, nk);
        }
        CPCOMMIT();
    }
    float* Cp = g_o + (size_t)b * HW * CCH;
    int m0 = blockIdx.x * 128, n0 = blockIdx.y * 128;
    #pragma unroll
    for (int mi = 0; mi < 4; mi++)
        #pragma unroll
        for (int nj = 0; nj < 4; nj++) {
            int r = m0 + wm + mi * 16 + g;
            int c = n0 + wn + nj * 8 + 2 * tig;
            *(float2*)&Cp[(size_t)r * CCH + c] =
                make_float2(acc[mi][nj][0], acc[mi][nj][1]);
            *(float2*)&Cp[(size_t)(r + 8) * CCH + c] =
                make_float2(acc[mi][nj][2], acc[mi][nj][3]);
        }
}

// ------ Proj+residual: out[o,m] = x[o,m] + sum_c O[m,c]Wp[o,c]+bp[o] ---------
__global__ __launch_bounds__(256, 2)
void proj_mma_kernel(const float* __restrict__ Wp, const float* __restrict__ bp,
                     const float* __restrict__ x, float* __restrict__ out) {
    extern __shared__ float smem[];
    int b = blockIdx.z;
    const float* Ag = g_o + (size_t)b * HW * CCH + (size_t)blockIdx.x * 128 * CCH;
    const float* xb = x   + (size_t)b * CCH * HW;
    float* ob = out + (size_t)b * CCH * HW;
    int n0 = blockIdx.y * 128, m0 = blockIdx.x * 128;
    int tid = threadIdx.x;
    int lane = tid & 31, warp = tid >> 5;
    int g = lane >> 2, tig = lane & 3;
    int wm = (warp >> 2) * 64, wn = (warp & 3) * 32;
    int brow = tid >> 2, bcol = (tid & 3) << 2;

    float acc[4][4][4];
    #pragma unroll
    for (int i = 0; i < 4; i++)
        #pragma unroll
        for (int j = 0; j < 4; j++)
            #pragma unroll
            for (int t = 0; t < 4; t++) acc[i][j][t] = 0.f;

    const int NT = CCH / 16;
    #pragma unroll
    for (int s = 0; s < 2; s++) {
        float* As = smem + s * SC_STG;
        float* Bs = As + 128 * PMK;
        #pragma unroll
        for (int rr = 0; rr < 2; rr++) {
            int r = brow + rr * 64;
            CPA16(sptr(&As[r * PMK + bcol]), Ag + (size_t)r * CCH + s * 16 + bcol);
            CPA16(sptr(&Bs[r * PMK + bcol]), Wp + (size_t)(n0 + r) * CCH + s * 16 + bcol);
        }
        CPCOMMIT();
    }
    for (int kt = 0; kt < NT; kt++) {
        CPWAIT1();
        __syncthreads();
        const float* Ab = smem + (kt % 3) * SC_STG;
        const float* Bb = Ab + 128 * PMK;
        unsigned af[4][4], bf[4][2];
        LOAD_AF_MK(af, Ab, 0, wm);
        LOAD_BF_MK(bf, Bb, 0, wn);
        MMA_ALL8(acc, af, bf);
        LOAD_AF_MK(af, Ab, 8, wm);
        LOAD_BF_MK(bf, Bb, 8, wn);
        MMA_ALL8(acc, af, bf);
        int nk = kt + 2;
        if (nk < NT) {
            float* As = smem + (nk % 3) * SC_STG;
            float* Bs = As + 128 * PMK;
            #pragma unroll
            for (int rr = 0; rr < 2; rr++) {
                int r = brow + rr * 64;
                CPA16(sptr(&As[r * PMK + bcol]), Ag + (size_t)r * CCH + nk * 16 + bcol);
                CPA16(sptr(&Bs[r * PMK + bcol]), Wp + (size_t)(n0 + r) * CCH + nk * 16 + bcol);
            }
        }
        CPCOMMIT();
    }
    #pragma unroll
    for (int nj = 0; nj < 4; nj++) {
        int c0 = n0 + wn + nj * 8 + 2 * tig;
        float bv0 = bp[c0], bv1 = bp[c0 + 1];
        #pragma unroll
        for (int mi = 0; mi < 4; mi++) {
            int r = m0 + wm + mi * 16 + g;
            ob[(size_t)c0 * HW + r]           = xb[(size_t)c0 * HW + r]           + acc[mi][nj][0] + bv0;
            ob[(size_t)(c0 + 1) * HW + r]     = xb[(size_t)(c0 + 1) * HW + r]     + acc[mi][nj][1] + bv1;
            ob[(size_t)c0 * HW + r + 8]       = xb[(size_t)c0 * HW + r + 8]       + acc[mi][nj][2] + bv0;
            ob[(size_t)(c0 + 1) * HW + r + 8] = xb[(size_t)(c0 + 1) * HW + r + 8] + acc[mi][nj][3] + bv1;
        }
    }
}

// ------------------------------ launch ---------------------------------------
extern "C" void kernel_launch(void* const* d_in, const int* in_sizes, int n_in,
                              void* d_out, int out_size) {
    const float* x  = (const float*)d_in[0];
    const float* nw = (const float*)d_in[1];
    const float* nb = (const float*)d_in[2];
    const float* wq = (const float*)d_in[3];
    const float* bq = (const float*)d_in[4];
    const float* wk = (const float*)d_in[5];
    const float* bk = (const float*)d_in[6];
    const float* wv = (const float*)d_in[7];
    const float* bv = (const float*)d_in[8];
    const float* wp = (const float*)d_in[9];
    const float* bp = (const float*)d_in[10];
    float* out = (float*)d_out;

    static int attr_done = 0;
    if (!attr_done) {
        cudaFuncSetAttribute(qkv_mma_kernel,
                             cudaFuncAttributeMaxDynamicSharedMemorySize, QKV_DYN);
        cudaFuncSetAttribute(scores_bf16_kernel,
                             cudaFuncAttributeMaxDynamicSharedMemorySize, O_DYN_B);
        cudaFuncSetAttribute(o_bf16_kernel,
                             cudaFuncAttributeMaxDynamicSharedMemorySize, O_DYN_B);
        cudaFuncSetAttribute(proj_mma_kernel,
                             cudaFuncAttributeMaxDynamicSharedMemorySize, SC_DYN);
        attr_done = 1;
    }

    groupnorm_kernel<<<BATCH * NGRP, 256>>>(x, nw, nb);

    dim3 gqkv(HW / 128, 3 * CCH / 128, BATCH);  // 32 x 12 x 2
    qkv_mma_kernel<<<gqkv, 256, QKV_DYN>>>(wq, bq, wk, bk, wv, bv);

    dim3 gsc(HW / 128, HW / 128, BATCH);        // 32 x 32 x 2
    scores_bf16_kernel<<<gsc, 256, O_DYN_B>>>();

    dim3 gzc(HW / 512, HW / ZROWBLK, BATCH);    // 8 x 64 x 2
    zcolsum_kernel<<<gzc, 256>>>();
    zfin_kernel<<<(BATCH * HW) / 256, 256>>>();
    vscale_kernel<<<(BATCH * CCH * HW) / (4 * 256), 256>>>();

    dim3 go(HW / 128, CCH / 128, BATCH);        // 32 x 4 x 2
    o_bf16_kernel<<<go, 256, O_DYN_B>>>();

    proj_mma_kernel<<<go, 256, SC_DYN>>>(wp, bp, x, out);
}

// round 14
// speedup vs baseline: 1.5662x; 1.0729x over previous
#include <cuda_runtime.h>
#include <cuda_bf16.h>
#include <math.h>
#include <float.h>
#include <stdint.h>

#define BATCH 2
#define CCH   512
#define HW    4096
#define NGRP  32
#define CPG   16
#define GRPELEM (CPG * HW)   // 65536

// bf16 GEMM geometry: k-chunk 32, rows padded to 20 words (40 bf16, 80 B)
#define OROWW 20
#define O_STG_WORDS (2 * 128 * OROWW)
#define O_STG_BYTES (O_STG_WORDS * 4)
#define O_DYN_B (3 * O_STG_BYTES)          // 61440 B

#define ZROWBLK 64   // rows per zcolsum CTA

// ---------------- scratch (static device globals; no allocation) -------------
__device__ float         g_hn  [(size_t)BATCH * CCH * HW];  // normed [b][c][n] fp32
__device__ __nv_bfloat16 g_hb  [(size_t)BATCH * HW * CCH];  // normed [b][n][c] bf16
__device__ __nv_bfloat16 g_wb  [4 * (size_t)CCH * CCH];     // wq,wk,wv,wp bf16
__device__ __nv_bfloat16 g_q   [(size_t)BATCH * HW * CCH];  // [b][i][c] bf16
__device__ __nv_bfloat16 g_k   [(size_t)BATCH * HW * CCH];  // [b][j][c] bf16
__device__ float         g_vt  [(size_t)BATCH * CCH * HW];  // [b][c][i] fp32
__device__ __nv_bfloat16 g_vb  [(size_t)BATCH * CCH * HW];  // [b][c][i] bf16 * 1/Z_i
__device__ __nv_bfloat16 g_s   [(size_t)BATCH * HW * HW];   // E'[j][i] = exp(scale*S^T)
__device__ __nv_bfloat16 g_ob  [(size_t)BATCH * HW * CCH];  // attn out [b][j][c] bf16
__device__ float         g_zp  [(size_t)BATCH * (HW / ZROWBLK) * HW]; // partials
__device__ float         g_z   [(size_t)BATCH * HW];        // 1/Z_i

// ------------------------------ helpers --------------------------------------
__device__ __forceinline__ void mma16(float* d, const unsigned* a, const unsigned* b) {
    asm volatile(
        "mma.sync.aligned.m16n8k16.row.col.f32.bf16.bf16.f32 "
        "{%0,%1,%2,%3}, {%4,%5,%6,%7}, {%8,%9}, {%0,%1,%2,%3};\n"
        : "+f"(d[0]), "+f"(d[1]), "+f"(d[2]), "+f"(d[3])
        : "r"(a[0]), "r"(a[1]), "r"(a[2]), "r"(a[3]), "r"(b[0]), "r"(b[1]));
}
__device__ __forceinline__ unsigned sptr(const void* p) {
    return (unsigned)__cvta_generic_to_shared(p);
}
#define CPA16(dst, src) asm volatile("cp.async.ca.shared.global [%0], [%1], 16;\n" :: "r"(dst), "l"(src))
#define CPCOMMIT()      asm volatile("cp.async.commit_group;\n")
#define CPWAIT1()       asm volatile("cp.async.wait_group 1;\n" ::: "memory")

// ---------------------------- GroupNorm --------------------------------------
__global__ void groupnorm_kernel(const float* __restrict__ x,
                                 const float* __restrict__ gw,
                                 const float* __restrict__ gb) {
    int b = blockIdx.x >> 5;
    int g = blockIdx.x & 31;
    const float4* xp = (const float4*)(x    + ((size_t)b * CCH + g * CPG) * HW);
    float4*       op = (float4*)      (g_hn + ((size_t)b * CCH + g * CPG) * HW);
    int tid = threadIdx.x;

    float s = 0.f, ss = 0.f;
    for (int i = tid; i < GRPELEM / 4; i += 256) {
        float4 v = xp[i];
        s  += v.x + v.y + v.z + v.w;
        ss += v.x * v.x + v.y * v.y + v.z * v.z + v.w * v.w;
    }
    __shared__ float shs[8], shss[8];
    #pragma unroll
    for (int o = 16; o; o >>= 1) {
        s  += __shfl_xor_sync(0xffffffffu, s,  o);
        ss += __shfl_xor_sync(0xffffffffu, ss, o);
    }
    if ((tid & 31) == 0) { shs[tid >> 5] = s; shss[tid >> 5] = ss; }
    __syncthreads();
    __shared__ float sm, sr;
    if (tid == 0) {
        float S = 0.f, SS = 0.f;
        #pragma unroll
        for (int i = 0; i < 8; i++) { S += shs[i]; SS += shss[i]; }
        float mean = S / (float)GRPELEM;
        float var  = SS / (float)GRPELEM - mean * mean;
        sm = mean;
        sr = rsqrtf(var + 1e-6f);
    }
    __syncthreads();
    float mean = sm, rstd = sr;
    for (int i = tid; i < GRPELEM / 4; i += 256) {
        int cl = i >> 10;
        float sc = gw[g * CPG + cl] * rstd;
        float sh = gb[g * CPG + cl] - mean * sc;
        float4 v = xp[i];
        v.x = v.x * sc + sh; v.y = v.y * sc + sh;
        v.z = v.z * sc + sh; v.w = v.w * sc + sh;
        op[i] = v;
    }
}

// ------- transpose normed activations: g_hn [c][n] fp32 -> g_hb [n][c] bf16 --
__global__ void hb_transpose_kernel() {
    __shared__ float tile[32][33];
    int b = blockIdx.z;
    int c0 = blockIdx.y * 32, n0 = blockIdx.x * 32;
    int tx = threadIdx.x & 31, ty = threadIdx.x >> 5;   // 256 thr: ty 0..7
    const float* src = g_hn + ((size_t)b * CCH + c0) * HW + n0;
    #pragma unroll
    for (int r = ty; r < 32; r += 8)
        tile[r][tx] = src[(size_t)r * HW + tx];
    __syncthreads();
    __nv_bfloat16* dst = g_hb + ((size_t)b * HW + n0) * CCH + c0;
    #pragma unroll
    for (int r = ty; r < 32; r += 8)
        dst[(size_t)r * CCH + tx] = __float2bfloat16(tile[tx][r]);
}

// ------- convert weights to bf16: g_wb[which] = bf16(w) ----------------------
__global__ void wcvt_kernel(const float* __restrict__ wq, const float* __restrict__ wk,
                            const float* __restrict__ wv, const float* __restrict__ wp) {
    int idx = blockIdx.x * 256 + threadIdx.x;         // float4 index
    int which = idx / (CCH * CCH / 4);
    int off   = idx % (CCH * CCH / 4);
    const float* src = which == 0 ? wq : which == 1 ? wk : which == 2 ? wv : wp;
    float4 v = ((const float4*)src)[off];
    __nv_bfloat162* d = (__nv_bfloat162*)(g_wb + (size_t)which * CCH * CCH) + off * 2;
    d[0] = __floats2bfloat162_rn(v.x, v.y);
    d[1] = __floats2bfloat162_rn(v.z, v.w);
}

// ---- bf16 MK-tile mainloop body (both operands [128 rows][32 bf16], 80B pitch)
#define BF16_CHUNK_MMAS(acc, At, Bt)  do {                                     \
    _Pragma("unroll")                                                          \
    for (int kk = 0; kk < 2; kk++) {                                           \
        unsigned af[4][4], bf[4][2];                                           \
        _Pragma("unroll")                                                      \
        for (int mi = 0; mi < 4; mi++) {                                       \
            int mb = wm + mi * 16 + g;                                         \
            af[mi][0] = (At)[mb * OROWW + kk * 8 + tig];                       \
            af[mi][1] = (At)[(mb + 8) * OROWW + kk * 8 + tig];                 \
            af[mi][2] = (At)[mb * OROWW + kk * 8 + tig + 4];                   \
            af[mi][3] = (At)[(mb + 8) * OROWW + kk * 8 + tig + 4];             \
        }                                                                      \
        _Pragma("unroll")                                                      \
        for (int nj = 0; nj < 4; nj++) {                                       \
            int nb = wn + nj * 8 + g;                                          \
            bf[nj][0] = (Bt)[nb * OROWW + kk * 8 + tig];                       \
            bf[nj][1] = (Bt)[nb * OROWW + kk * 8 + tig + 4];                   \
        }                                                                      \
        _Pragma("unroll")                                                      \
        for (int mi = 0; mi < 4; mi++)                                         \
            _Pragma("unroll")                                                  \
            for (int nj = 0; nj < 4; nj++) mma16((acc)[mi][nj], af[mi], bf[nj]); \
    } } while (0)

#define BF16_LOAD_STAGE(st, Ag, Astr, Bg, Bstr, ck) do {                       \
    const __nv_bfloat16* as = (Ag) + (size_t)lrow * (Astr) + (ck) * 32 + lh * 16; \
    const __nv_bfloat16* bs = (Bg) + (size_t)lrow * (Bstr) + (ck) * 32 + lh * 16; \
    CPA16((st) + lrow * 80 + lh * 32,              as);                        \
    CPA16((st) + lrow * 80 + lh * 32 + 16,         as + 8);                    \
    CPA16((st) + 10240 + lrow * 80 + lh * 32,      bs);                        \
    CPA16((st) + 10240 + lrow * 80 + lh * 32 + 16, bs + 8);                    \
    } while (0)

#define BF16_PREAMBLE()                                                        \
    int tid = threadIdx.x;                                                     \
    int lane = tid & 31, warp = tid >> 5;                                      \
    int g = lane >> 2, tig = lane & 3;                                         \
    int wm = (warp >> 2) * 64, wn = (warp & 3) * 32;                           \
    int lrow = tid >> 1, lh = tid & 1;                                         \
    float acc[4][4][4];                                                        \
    _Pragma("unroll")                                                          \
    for (int i = 0; i < 4; i++)                                                \
        _Pragma("unroll")                                                      \
        for (int j = 0; j < 4; j++)                                            \
            _Pragma("unroll")                                                  \
            for (int t = 0; t < 4; t++) acc[i][j][t] = 0.f;

// -------- QKV GEMM (bf16, merged): C[m,n] = sum_c Hb[m,c]*W[n,c] + bias[n] ---
// which 0 -> g_q bf16 [i][c], 1 -> g_k bf16 [j][c], 2 -> g_vt fp32 [c][i]
__global__ __launch_bounds__(256, 2)
void qkv_bf16_kernel(const float* __restrict__ bq, const float* __restrict__ bk,
                     const float* __restrict__ bv) {
    extern __shared__ unsigned ssm[];
    int b = blockIdx.z;
    int which = blockIdx.y >> 2;
    int n0 = (blockIdx.y & 3) * 128, m0 = blockIdx.x * 128;
    const __nv_bfloat16* Ag = g_hb + (size_t)b * HW * CCH + (size_t)m0 * CCH;
    const __nv_bfloat16* Bg = g_wb + (size_t)which * CCH * CCH + (size_t)n0 * CCH;
    const float* bias = which == 0 ? bq : which == 1 ? bk : bv;
    uint32_t sbase = sptr(ssm);
    BF16_PREAMBLE();

    const int NC = CCH / 32;   // 16
    #pragma unroll
    for (int s = 0; s < 2; s++) {
        BF16_LOAD_STAGE(sbase + s * O_STG_BYTES, Ag, CCH, Bg, CCH, s);
        CPCOMMIT();
    }
    for (int kt = 0; kt < NC; kt++) {
        CPWAIT1();
        __syncthreads();
        const unsigned* At = ssm + (kt % 3) * O_STG_WORDS;
        const unsigned* Bt = At + 128 * OROWW;
        BF16_CHUNK_MMAS(acc, At, Bt);
        int nk = kt + 2;
        if (nk < NC) {
            BF16_LOAD_STAGE(sbase + (nk % 3) * O_STG_BYTES, Ag, CCH, Bg, CCH, nk);
        }
        CPCOMMIT();
    }
    if (which == 2) {
        float* Vt = g_vt + (size_t)b * CCH * HW;
        #pragma unroll
        for (int mi = 0; mi < 4; mi++)
            #pragma unroll
            for (int nj = 0; nj < 4; nj++) {
                int r = m0 + wm + mi * 16 + g;
                int c = n0 + wn + nj * 8 + 2 * tig;
                float bv0 = bias[c], bv1 = bias[c + 1];
                Vt[(size_t)c * HW + r]           = acc[mi][nj][0] + bv0;
                Vt[(size_t)(c + 1) * HW + r]     = acc[mi][nj][1] + bv1;
                Vt[(size_t)c * HW + r + 8]       = acc[mi][nj][2] + bv0;
                Vt[(size_t)(c + 1) * HW + r + 8] = acc[mi][nj][3] + bv1;
            }
    } else {
        __nv_bfloat16* Cp = (which == 0 ? g_q : g_k) + (size_t)b * HW * CCH;
        #pragma unroll
        for (int mi = 0; mi < 4; mi++)
            #pragma unroll
            for (int nj = 0; nj < 4; nj++) {
                int r = m0 + wm + mi * 16 + g;
                int c = n0 + wn + nj * 8 + 2 * tig;
                float bv0 = bias[c], bv1 = bias[c + 1];
                *(__nv_bfloat162*)&Cp[(size_t)r * CCH + c] =
                    __floats2bfloat162_rn(acc[mi][nj][0] + bv0, acc[mi][nj][1] + bv1);
                *(__nv_bfloat162*)&Cp[(size_t)(r + 8) * CCH + c] =
                    __floats2bfloat162_rn(acc[mi][nj][2] + bv0, acc[mi][nj][3] + bv1);
            }
    }
}

// -------- Scores (bf16): E'[j,i] = exp(scale * K_j . Q_i) -> bf16 ------------
__global__ __launch_bounds__(256, 2)
void scores_bf16_kernel() {
    extern __shared__ unsigned ssm[];
    int b = blockIdx.z;
    const __nv_bfloat16* Ag = g_k + (size_t)b * HW * CCH + (size_t)(blockIdx.x * 128) * CCH;
    const __nv_bfloat16* Bg = g_q + (size_t)b * HW * CCH + (size_t)(blockIdx.y * 128) * CCH;
    uint32_t sbase = sptr(ssm);
    BF16_PREAMBLE();

    const int NC = CCH / 32;   // 16
    #pragma unroll
    for (int s = 0; s < 2; s++) {
        BF16_LOAD_STAGE(sbase + s * O_STG_BYTES, Ag, CCH, Bg, CCH, s);
        CPCOMMIT();
    }
    for (int kt = 0; kt < NC; kt++) {
        CPWAIT1();
        __syncthreads();
        const unsigned* At = ssm + (kt % 3) * O_STG_WORDS;
        const unsigned* Bt = At + 128 * OROWW;
        BF16_CHUNK_MMAS(acc, At, Bt);
        int nk = kt + 2;
        if (nk < NC) {
            BF16_LOAD_STAGE(sbase + (nk % 3) * O_STG_BYTES, Ag, CCH, Bg, CCH, nk);
        }
        CPCOMMIT();
    }
    const float scale = 0.04419417382415922f;   // 512^-0.5
    __nv_bfloat16* Cp = g_s + (size_t)b * HW * HW;
    int m0 = blockIdx.x * 128, n0 = blockIdx.y * 128;
    #pragma unroll
    for (int mi = 0; mi < 4; mi++)
        #pragma unroll
        for (int nj = 0; nj < 4; nj++) {
            int r = m0 + wm + mi * 16 + g;
            int c = n0 + wn + nj * 8 + 2 * tig;
            *(__nv_bfloat162*)&Cp[(size_t)r * HW + c] =
                __floats2bfloat162_rn(__expf(acc[mi][nj][0] * scale),
                                      __expf(acc[mi][nj][1] * scale));
            *(__nv_bfloat162*)&Cp[(size_t)(r + 8) * HW + c] =
                __floats2bfloat162_rn(__expf(acc[mi][nj][2] * scale),
                                      __expf(acc[mi][nj][3] * scale));
        }
}

// ------- column sums of E' stage 1: each CTA sums 64 rows x 512 cols ---------
__global__ void zcolsum_kernel() {
    int b = blockIdx.z;
    const __nv_bfloat162* S = (const __nv_bfloat162*)(g_s + (size_t)b * HW * HW);
    int t = threadIdx.x;
    size_t rowstride = HW / 2;
    const __nv_bfloat162* p = S + (size_t)(blockIdx.y * ZROWBLK) * rowstride
                                + blockIdx.x * 256 + t;
    float sx[8], sy[8];
    #pragma unroll
    for (int u = 0; u < 8; u++) { sx[u] = 0.f; sy[u] = 0.f; }
    #pragma unroll
    for (int jj = 0; jj < ZROWBLK / 8; jj++) {
        #pragma unroll
        for (int u = 0; u < 8; u++) {
            float2 v = __bfloat1622float2(p[(size_t)(jj * 8 + u) * rowstride]);
            sx[u] += v.x; sy[u] += v.y;
        }
    }
    float fx = (sx[0] + sx[1]) + (sx[2] + sx[3]) + ((sx[4] + sx[5]) + (sx[6] + sx[7]));
    float fy = (sy[0] + sy[1]) + (sy[2] + sy[3]) + ((sy[4] + sy[5]) + (sy[6] + sy[7]));
    float* zp = g_zp + ((size_t)(b * (HW / ZROWBLK) + blockIdx.y)) * HW
              + (size_t)(blockIdx.x * 256 + t) * 2;
    zp[0] = fx; zp[1] = fy;
}

// ------- stage 2: combine partials, reciprocal -------------------------------
__global__ void zfin_kernel() {
    int idx = blockIdx.x * 256 + threadIdx.x;   // < BATCH*HW
    int b = idx >> 12, i = idx & (HW - 1);
    const float* zp = g_zp + (size_t)b * (HW / ZROWBLK) * HW + i;
    float s0 = 0.f, s1 = 0.f, s2 = 0.f, s3 = 0.f;
    #pragma unroll
    for (int p = 0; p < HW / ZROWBLK; p += 4) {
        s0 += zp[(size_t)(p + 0) * HW];
        s1 += zp[(size_t)(p + 1) * HW];
        s2 += zp[(size_t)(p + 2) * HW];
        s3 += zp[(size_t)(p + 3) * HW];
    }
    g_z[idx] = 1.f / ((s0 + s1) + (s2 + s3));
}

// ------- V-hat: g_vb[c][i] = bf16(g_vt[c][i] * g_z[i]) -----------------------
__global__ void vscale_kernel() {
    size_t idx4 = (size_t)blockIdx.x * 256 + threadIdx.x;
    int b = (int)(idx4 / ((size_t)CCH * (HW / 4)));
    size_t rem = idx4 - (size_t)b * CCH * (HW / 4);
    int i4 = (int)(rem % (HW / 4));
    float4 v = ((const float4*)g_vt)[idx4];
    float4 z = ((const float4*)g_z)[(size_t)b * (HW / 4) + i4];
    __nv_bfloat162* o = ((__nv_bfloat162*)g_vb) + idx4 * 2;
    o[0] = __floats2bfloat162_rn(v.x * z.x, v.y * z.y);
    o[1] = __floats2bfloat162_rn(v.z * z.z, v.w * z.w);
}

// ------ O GEMM (bf16): O[j,c] = sum_i E'[j,i] * Vhat[c,i] -> bf16 ------------
__global__ __launch_bounds__(256, 2)
void o_bf16_kernel() {
    extern __shared__ unsigned osm[];
    int b = blockIdx.z;
    const __nv_bfloat16* Ag = g_s  + (size_t)b * HW * HW + (size_t)(blockIdx.x * 128) * HW;
    const __nv_bfloat16* Bg = g_vb + (size_t)b * CCH * HW + (size_t)(blockIdx.y * 128) * HW;
    uint32_t sbase = sptr(osm);
    BF16_PREAMBLE();

    const int NC = HW / 32;
    #pragma unroll
    for (int s = 0; s < 2; s++) {
        BF16_LOAD_STAGE(sbase + s * O_STG_BYTES, Ag, HW, Bg, HW, s);
        CPCOMMIT();
    }
    for (int kt = 0; kt < NC; kt++) {
        CPWAIT1();
        __syncthreads();
        const unsigned* At = osm + (kt % 3) * O_STG_WORDS;
        const unsigned* Bt = At + 128 * OROWW;
        BF16_CHUNK_MMAS(acc, At, Bt);
        int nk = kt + 2;
        if (nk < NC) {
            BF16_LOAD_STAGE(sbase + (nk % 3) * O_STG_BYTES, Ag, HW, Bg, HW, nk);
        }
        CPCOMMIT();
    }
    __nv_bfloat16* Cp = g_ob + (size_t)b * HW * CCH;
    int m0 = blockIdx.x * 128, n0 = blockIdx.y * 128;
    #pragma unroll
    for (int mi = 0; mi < 4; mi++)
        #pragma unroll
        for (int nj = 0; nj < 4; nj++) {
            int r = m0 + wm + mi * 16 + g;
            int c = n0 + wn + nj * 8 + 2 * tig;
            *(__nv_bfloat162*)&Cp[(size_t)r * CCH + c] =
                __floats2bfloat162_rn(acc[mi][nj][0], acc[mi][nj][1]);
            *(__nv_bfloat162*)&Cp[(size_t)(r + 8) * CCH + c] =
                __floats2bfloat162_rn(acc[mi][nj][2], acc[mi][nj][3]);
        }
}

// ------ Proj+residual (bf16): out[o,m] = x[o,m] + sum_c O[m,c]Wp[o,c]+bp[o] --
__global__ __launch_bounds__(256, 2)
void proj_bf16_kernel(const float* __restrict__ bp,
                      const float* __restrict__ x, float* __restrict__ out) {
    extern __shared__ unsigned ssm[];
    int b = blockIdx.z;
    int n0 = blockIdx.y * 128, m0 = blockIdx.x * 128;
    const __nv_bfloat16* Ag = g_ob + (size_t)b * HW * CCH + (size_t)m0 * CCH;
    const __nv_bfloat16* Bg = g_wb + (size_t)3 * CCH * CCH + (size_t)n0 * CCH;
    const float* xb = x   + (size_t)b * CCH * HW;
    float* ob = out + (size_t)b * CCH * HW;
    uint32_t sbase = sptr(ssm);
    BF16_PREAMBLE();

    const int NC = CCH / 32;   // 16
    #pragma unroll
    for (int s = 0; s < 2; s++) {
        BF16_LOAD_STAGE(sbase + s * O_STG_BYTES, Ag, CCH, Bg, CCH, s);
        CPCOMMIT();
    }
    for (int kt = 0; kt < NC; kt++) {
        CPWAIT1();
        __syncthreads();
        const unsigned* At = ssm + (kt % 3) * O_STG_WORDS;
        const unsigned* Bt = At + 128 * OROWW;
        BF16_CHUNK_MMAS(acc, At, Bt);
        int nk = kt + 2;
        if (nk < NC) {
            BF16_LOAD_STAGE(sbase + (nk % 3) * O_STG_BYTES, Ag, CCH, Bg, CCH, nk);
        }
        CPCOMMIT();
    }
    #pragma unroll
    for (int nj = 0; nj < 4; nj++) {
        int c0 = n0 + wn + nj * 8 + 2 * tig;
        float bv0 = bp[c0], bv1 = bp[c0 + 1];
        #pragma unroll
        for (int mi = 0; mi < 4; mi++) {
            int r = m0 + wm + mi * 16 + g;
            ob[(size_t)c0 * HW + r]           = xb[(size_t)c0 * HW + r]           + acc[mi][nj][0] + bv0;
            ob[(size_t)(c0 + 1) * HW + r]     = xb[(size_t)(c0 + 1) * HW + r]     + acc[mi][nj][1] + bv1;
            ob[(size_t)c0 * HW + r + 8]       = xb[(size_t)c0 * HW + r + 8]       + acc[mi][nj][2] + bv0;
            ob[(size_t)(c0 + 1) * HW + r + 8] = xb[(size_t)(c0 + 1) * HW + r + 8] + acc[mi][nj][3] + bv1;
        }
    }
}

// ------------------------------ launch ---------------------------------------
extern "C" void kernel_launch(void* const* d_in, const int* in_sizes, int n_in,
                              void* d_out, int out_size) {
    const float* x  = (const float*)d_in[0];
    const float* nw = (const float*)d_in[1];
    const float* nb = (const float*)d_in[2];
    const float* wq = (const float*)d_in[3];
    const float* bq = (const float*)d_in[4];
    const float* wk = (const float*)d_in[5];
    const float* bk = (const float*)d_in[6];
    const float* wv = (const float*)d_in[7];
    const float* bv = (const float*)d_in[8];
    const float* wp = (const float*)d_in[9];
    const float* bp = (const float*)d_in[10];
    float* out = (float*)d_out;

    static int attr_done = 0;
    if (!attr_done) {
        cudaFuncSetAttribute(qkv_bf16_kernel,
                             cudaFuncAttributeMaxDynamicSharedMemorySize, O_DYN_B);
        cudaFuncSetAttribute(scores_bf16_kernel,
                             cudaFuncAttributeMaxDynamicSharedMemorySize, O_DYN_B);
        cudaFuncSetAttribute(o_bf16_kernel,
                             cudaFuncAttributeMaxDynamicSharedMemorySize, O_DYN_B);
        cudaFuncSetAttribute(proj_bf16_kernel,
                             cudaFuncAttributeMaxDynamicSharedMemorySize, O_DYN_B);
        attr_done = 1;
    }

    groupnorm_kernel<<<BATCH * NGRP, 256>>>(x, nw, nb);

    wcvt_kernel<<<(4 * CCH * CCH / 4) / 256, 256>>>(wq, wk, wv, wp);

    dim3 gtr(HW / 32, CCH / 32, BATCH);         // 128 x 16 x 2
    hb_transpose_kernel<<<gtr, 256>>>();

    dim3 gqkv(HW / 128, 3 * CCH / 128, BATCH);  // 32 x 12 x 2
    qkv_bf16_kernel<<<gqkv, 256, O_DYN_B>>>(bq, bk, bv);

    dim3 gsc(HW / 128, HW / 128, BATCH);        // 32 x 32 x 2
    scores_bf16_kernel<<<gsc, 256, O_DYN_B>>>();

    dim3 gzc(HW / 512, HW / ZROWBLK, BATCH);    // 8 x 64 x 2
    zcolsum_kernel<<<gzc, 256>>>();
    zfin_kernel<<<(BATCH * HW) / 256, 256>>>();
    vscale_kernel<<<(BATCH * CCH * HW) / (4 * 256), 256>>>();

    dim3 go(HW / 128, CCH / 128, BATCH);        // 32 x 4 x 2
    o_bf16_kernel<<<go, 256, O_DYN_B>>>();

    proj_bf16_kernel<<<go, 256, O_DYN_B>>>(bp, x, out);
}

// round 15
// speedup vs baseline: 1.8391x; 1.1743x over previous
#include <cuda_runtime.h>
#include <cuda_bf16.h>
#include <math.h>
#include <float.h>
#include <stdint.h>

#define BATCH 2
#define CCH   512
#define HW    4096
#define NGRP  32
#define CPG   16
#define GRPELEM (CPG * HW)   // 65536

// bf16 GEMM geometry: k-chunk 32, rows padded to 20 words (40 bf16, 80 B)
#define OROWW 20
#define O_STG_WORDS (2 * 128 * OROWW)
#define O_STG_BYTES (O_STG_WORDS * 4)
#define O_DYN_B (3 * O_STG_BYTES)          // 61440 B

#define ZROWBLK 64   // rows per zcolsum CTA

// ---------------- scratch (static device globals; no allocation) -------------
__device__ float         g_hn  [(size_t)BATCH * CCH * HW];  // normed [b][c][n] fp32
__device__ __nv_bfloat16 g_hb  [(size_t)BATCH * HW * CCH];  // normed [b][n][c] bf16
__device__ __nv_bfloat16 g_wb  [4 * (size_t)CCH * CCH];     // wq,wk,wv,wp bf16
__device__ __nv_bfloat16 g_q   [(size_t)BATCH * HW * CCH];  // [b][i][c] bf16
__device__ __nv_bfloat16 g_k   [(size_t)BATCH * HW * CCH];  // [b][j][c] bf16
__device__ float         g_vt  [(size_t)BATCH * CCH * HW];  // [b][c][i] fp32
__device__ __nv_bfloat16 g_vb  [(size_t)BATCH * CCH * HW];  // [b][c][i] bf16 * 1/Z_i
__device__ __nv_bfloat16 g_s   [(size_t)BATCH * HW * HW];   // E'[j][i] = exp(scale*S^T)
__device__ __nv_bfloat16 g_ob  [(size_t)BATCH * HW * CCH];  // attn out [b][j][c] bf16
__device__ float         g_zp  [(size_t)BATCH * (HW / ZROWBLK) * HW]; // partials
__device__ float         g_z   [(size_t)BATCH * HW];        // 1/Z_i

// ------------------------------ helpers --------------------------------------
__device__ __forceinline__ void mma16(float* d, const unsigned* a, const unsigned* b) {
    asm volatile(
        "mma.sync.aligned.m16n8k16.row.col.f32.bf16.bf16.f32 "
        "{%0,%1,%2,%3}, {%4,%5,%6,%7}, {%8,%9}, {%0,%1,%2,%3};\n"
        : "+f"(d[0]), "+f"(d[1]), "+f"(d[2]), "+f"(d[3])
        : "r"(a[0]), "r"(a[1]), "r"(a[2]), "r"(a[3]), "r"(b[0]), "r"(b[1]));
}
__device__ __forceinline__ void ldsm4(unsigned* r, uint32_t addr) {
    asm volatile(
        "ldmatrix.sync.aligned.m8n8.x4.shared.b16 {%0,%1,%2,%3}, [%4];"
        : "=r"(r[0]), "=r"(r[1]), "=r"(r[2]), "=r"(r[3]) : "r"(addr));
}
__device__ __forceinline__ unsigned sptr(const void* p) {
    return (unsigned)__cvta_generic_to_shared(p);
}
#define CPA16(dst, src) asm volatile("cp.async.ca.shared.global [%0], [%1], 16;\n" :: "r"(dst), "l"(src))
#define CPCOMMIT()      asm volatile("cp.async.commit_group;\n")
#define CPWAIT1()       asm volatile("cp.async.wait_group 1;\n" ::: "memory")

// ---------------------------- GroupNorm --------------------------------------
__global__ void groupnorm_kernel(const float* __restrict__ x,
                                 const float* __restrict__ gw,
                                 const float* __restrict__ gb) {
    int b = blockIdx.x >> 5;
    int g = blockIdx.x & 31;
    const float4* xp = (const float4*)(x    + ((size_t)b * CCH + g * CPG) * HW);
    float4*       op = (float4*)      (g_hn + ((size_t)b * CCH + g * CPG) * HW);
    int tid = threadIdx.x;

    float s = 0.f, ss = 0.f;
    for (int i = tid; i < GRPELEM / 4; i += 256) {
        float4 v = xp[i];
        s  += v.x + v.y + v.z + v.w;
        ss += v.x * v.x + v.y * v.y + v.z * v.z + v.w * v.w;
    }
    __shared__ float shs[8], shss[8];
    #pragma unroll
    for (int o = 16; o; o >>= 1) {
        s  += __shfl_xor_sync(0xffffffffu, s,  o);
        ss += __shfl_xor_sync(0xffffffffu, ss, o);
    }
    if ((tid & 31) == 0) { shs[tid >> 5] = s; shss[tid >> 5] = ss; }
    __syncthreads();
    __shared__ float sm, sr;
    if (tid == 0) {
        float S = 0.f, SS = 0.f;
        #pragma unroll
        for (int i = 0; i < 8; i++) { S += shs[i]; SS += shss[i]; }
        float mean = S / (float)GRPELEM;
        float var  = SS / (float)GRPELEM - mean * mean;
        sm = mean;
        sr = rsqrtf(var + 1e-6f);
    }
    __syncthreads();
    float mean = sm, rstd = sr;
    for (int i = tid; i < GRPELEM / 4; i += 256) {
        int cl = i >> 10;
        float sc = gw[g * CPG + cl] * rstd;
        float sh = gb[g * CPG + cl] - mean * sc;
        float4 v = xp[i];
        v.x = v.x * sc + sh; v.y = v.y * sc + sh;
        v.z = v.z * sc + sh; v.w = v.w * sc + sh;
        op[i] = v;
    }
}

// ------- transpose normed activations: g_hn [c][n] fp32 -> g_hb [n][c] bf16 --
__global__ void hb_transpose_kernel() {
    __shared__ float tile[32][33];
    int b = blockIdx.z;
    int c0 = blockIdx.y * 32, n0 = blockIdx.x * 32;
    int tx = threadIdx.x & 31, ty = threadIdx.x >> 5;   // 256 thr: ty 0..7
    const float* src = g_hn + ((size_t)b * CCH + c0) * HW + n0;
    #pragma unroll
    for (int r = ty; r < 32; r += 8)
        tile[r][tx] = src[(size_t)r * HW + tx];
    __syncthreads();
    __nv_bfloat16* dst = g_hb + ((size_t)b * HW + n0) * CCH + c0;
    #pragma unroll
    for (int r = ty; r < 32; r += 8)
        dst[(size_t)r * CCH + tx] = __float2bfloat16(tile[tx][r]);
}

// ------- convert weights to bf16: g_wb[which] = bf16(w) ----------------------
__global__ void wcvt_kernel(const float* __restrict__ wq, const float* __restrict__ wk,
                            const float* __restrict__ wv, const float* __restrict__ wp) {
    int idx = blockIdx.x * 256 + threadIdx.x;         // float4 index
    int which = idx / (CCH * CCH / 4);
    int off   = idx % (CCH * CCH / 4);
    const float* src = which == 0 ? wq : which == 1 ? wk : which == 2 ? wv : wp;
    float4 v = ((const float4*)src)[off];
    __nv_bfloat162* d = (__nv_bfloat162*)(g_wb + (size_t)which * CCH * CCH) + off * 2;
    d[0] = __floats2bfloat162_rn(v.x, v.y);
    d[1] = __floats2bfloat162_rn(v.z, v.w);
}

// ---- bf16 MK-tile mainloop body via ldmatrix (operands [128][32bf16], 80B) --
#define BF16_CHUNK_MMAS(acc, At_s, Bt_s)  do {                                 \
    _Pragma("unroll")                                                          \
    for (int kk = 0; kk < 2; kk++) {                                           \
        unsigned af[4][4], bf[4][2];                                           \
        _Pragma("unroll")                                                      \
        for (int mi = 0; mi < 4; mi++)                                         \
            ldsm4(af[mi], (At_s) +                                             \
                  4u * ((wm + mi * 16 + a_row) * OROWW + kk * 8 + a_kw));      \
        _Pragma("unroll")                                                      \
        for (int njp = 0; njp < 2; njp++)                                      \
            ldsm4(&bf[2 * njp][0], (Bt_s) +                                    \
                  4u * ((wn + njp * 16 + b_row) * OROWW + kk * 8 + b_kw));     \
        _Pragma("unroll")                                                      \
        for (int mi = 0; mi < 4; mi++)                                         \
            _Pragma("unroll")                                                  \
            for (int nj = 0; nj < 4; nj++) mma16((acc)[mi][nj], af[mi], bf[nj]); \
    } } while (0)

#define BF16_LOAD_STAGE(st, Ag, Astr, Bg, Bstr, ck) do {                       \
    const __nv_bfloat16* as = (Ag) + (size_t)lrow * (Astr) + (ck) * 32 + lh * 16; \
    const __nv_bfloat16* bs = (Bg) + (size_t)lrow * (Bstr) + (ck) * 32 + lh * 16; \
    CPA16((st) + lrow * 80 + lh * 32,              as);                        \
    CPA16((st) + lrow * 80 + lh * 32 + 16,         as + 8);                    \
    CPA16((st) + 10240 + lrow * 80 + lh * 32,      bs);                        \
    CPA16((st) + 10240 + lrow * 80 + lh * 32 + 16, bs + 8);                    \
    } while (0)

#define BF16_PREAMBLE()                                                        \
    int tid = threadIdx.x;                                                     \
    int lane = tid & 31, warp = tid >> 5;                                      \
    int g = lane >> 2, tig = lane & 3;                                         \
    int wm = (warp >> 2) * 64, wn = (warp & 3) * 32;                           \
    int lrow = tid >> 1, lh = tid & 1;                                         \
    int mat = lane >> 3, mr = lane & 7;                                        \
    int a_row = ((mat & 1) << 3) + mr, a_kw = (mat >> 1) << 2;                 \
    int b_row = ((mat >> 1) << 3) + mr, b_kw = (mat & 1) << 2;                 \
    (void)g; (void)tig;                                                        \
    float acc[4][4][4];                                                        \
    _Pragma("unroll")                                                          \
    for (int i = 0; i < 4; i++)                                                \
        _Pragma("unroll")                                                      \
        for (int j = 0; j < 4; j++)                                            \
            _Pragma("unroll")                                                  \
            for (int t = 0; t < 4; t++) acc[i][j][t] = 0.f;

// -------- QKV GEMM (bf16, merged): C[m,n] = sum_c Hb[m,c]*W[n,c] + bias[n] ---
// which 0 -> g_q bf16 [i][c], 1 -> g_k bf16 [j][c], 2 -> g_vt fp32 [c][i]
__global__ __launch_bounds__(256, 2)
void qkv_bf16_kernel(const float* __restrict__ bq, const float* __restrict__ bk,
                     const float* __restrict__ bv) {
    extern __shared__ unsigned ssm[];
    int b = blockIdx.z;
    int which = blockIdx.y >> 2;
    int n0 = (blockIdx.y & 3) * 128, m0 = blockIdx.x * 128;
    const __nv_bfloat16* Ag = g_hb + (size_t)b * HW * CCH + (size_t)m0 * CCH;
    const __nv_bfloat16* Bg = g_wb + (size_t)which * CCH * CCH + (size_t)n0 * CCH;
    const float* bias = which == 0 ? bq : which == 1 ? bk : bv;
    uint32_t sbase = sptr(ssm);
    BF16_PREAMBLE();

    const int NC = CCH / 32;   // 16
    #pragma unroll
    for (int s = 0; s < 2; s++) {
        BF16_LOAD_STAGE(sbase + s * O_STG_BYTES, Ag, CCH, Bg, CCH, s);
        CPCOMMIT();
    }
    for (int kt = 0; kt < NC; kt++) {
        CPWAIT1();
        __syncthreads();
        uint32_t At_s = sbase + (kt % 3) * O_STG_BYTES;
        uint32_t Bt_s = At_s + 10240;
        BF16_CHUNK_MMAS(acc, At_s, Bt_s);
        int nk = kt + 2;
        if (nk < NC) {
            BF16_LOAD_STAGE(sbase + (nk % 3) * O_STG_BYTES, Ag, CCH, Bg, CCH, nk);
        }
        CPCOMMIT();
    }
    if (which == 2) {
        float* Vt = g_vt + (size_t)b * CCH * HW;
        #pragma unroll
        for (int mi = 0; mi < 4; mi++)
            #pragma unroll
            for (int nj = 0; nj < 4; nj++) {
                int r = m0 + wm + mi * 16 + g;
                int c = n0 + wn + nj * 8 + 2 * tig;
                float bv0 = bias[c], bv1 = bias[c + 1];
                Vt[(size_t)c * HW + r]           = acc[mi][nj][0] + bv0;
                Vt[(size_t)(c + 1) * HW + r]     = acc[mi][nj][1] + bv1;
                Vt[(size_t)c * HW + r + 8]       = acc[mi][nj][2] + bv0;
                Vt[(size_t)(c + 1) * HW + r + 8] = acc[mi][nj][3] + bv1;
            }
    } else {
        __nv_bfloat16* Cp = (which == 0 ? g_q : g_k) + (size_t)b * HW * CCH;
        #pragma unroll
        for (int mi = 0; mi < 4; mi++)
            #pragma unroll
            for (int nj = 0; nj < 4; nj++) {
                int r = m0 + wm + mi * 16 + g;
                int c = n0 + wn + nj * 8 + 2 * tig;
                float bv0 = bias[c], bv1 = bias[c + 1];
                *(__nv_bfloat162*)&Cp[(size_t)r * CCH + c] =
                    __floats2bfloat162_rn(acc[mi][nj][0] + bv0, acc[mi][nj][1] + bv1);
                *(__nv_bfloat162*)&Cp[(size_t)(r + 8) * CCH + c] =
                    __floats2bfloat162_rn(acc[mi][nj][2] + bv0, acc[mi][nj][3] + bv1);
            }
    }
}

// -------- Scores (bf16): E'[j,i] = exp(scale * K_j . Q_i) -> bf16 ------------
__global__ __launch_bounds__(256, 2)
void scores_bf16_kernel() {
    extern __shared__ unsigned ssm[];
    int b = blockIdx.z;
    const __nv_bfloat16* Ag = g_k + (size_t)b * HW * CCH + (size_t)(blockIdx.x * 128) * CCH;
    const __nv_bfloat16* Bg = g_q + (size_t)b * HW * CCH + (size_t)(blockIdx.y * 128) * CCH;
    uint32_t sbase = sptr(ssm);
    BF16_PREAMBLE();

    const int NC = CCH / 32;   // 16
    #pragma unroll
    for (int s = 0; s < 2; s++) {
        BF16_LOAD_STAGE(sbase + s * O_STG_BYTES, Ag, CCH, Bg, CCH, s);
        CPCOMMIT();
    }
    for (int kt = 0; kt < NC; kt++) {
        CPWAIT1();
        __syncthreads();
        uint32_t At_s = sbase + (kt % 3) * O_STG_BYTES;
        uint32_t Bt_s = At_s + 10240;
        BF16_CHUNK_MMAS(acc, At_s, Bt_s);
        int nk = kt + 2;
        if (nk < NC) {
            BF16_LOAD_STAGE(sbase + (nk % 3) * O_STG_BYTES, Ag, CCH, Bg, CCH, nk);
        }
        CPCOMMIT();
    }
    const float scale = 0.04419417382415922f;   // 512^-0.5
    __nv_bfloat16* Cp = g_s + (size_t)b * HW * HW;
    int m0 = blockIdx.x * 128, n0 = blockIdx.y * 128;
    #pragma unroll
    for (int mi = 0; mi < 4; mi++)
        #pragma unroll
        for (int nj = 0; nj < 4; nj++) {
            int r = m0 + wm + mi * 16 + g;
            int c = n0 + wn + nj * 8 + 2 * tig;
            *(__nv_bfloat162*)&Cp[(size_t)r * HW + c] =
                __floats2bfloat162_rn(__expf(acc[mi][nj][0] * scale),
                                      __expf(acc[mi][nj][1] * scale));
            *(__nv_bfloat162*)&Cp[(size_t)(r + 8) * HW + c] =
                __floats2bfloat162_rn(__expf(acc[mi][nj][2] * scale),
                                      __expf(acc[mi][nj][3] * scale));
        }
}

// ------- column sums of E' stage 1: each CTA sums 64 rows x 512 cols ---------
__global__ void zcolsum_kernel() {
    int b = blockIdx.z;
    const __nv_bfloat162* S = (const __nv_bfloat162*)(g_s + (size_t)b * HW * HW);
    int t = threadIdx.x;
    size_t rowstride = HW / 2;
    const __nv_bfloat162* p = S + (size_t)(blockIdx.y * ZROWBLK) * rowstride
                                + blockIdx.x * 256 + t;
    float sx[8], sy[8];
    #pragma unroll
    for (int u = 0; u < 8; u++) { sx[u] = 0.f; sy[u] = 0.f; }
    #pragma unroll
    for (int jj = 0; jj < ZROWBLK / 8; jj++) {
        #pragma unroll
        for (int u = 0; u < 8; u++) {
            float2 v = __bfloat1622float2(p[(size_t)(jj * 8 + u) * rowstride]);
            sx[u] += v.x; sy[u] += v.y;
        }
    }
    float fx = (sx[0] + sx[1]) + (sx[2] + sx[3]) + ((sx[4] + sx[5]) + (sx[6] + sx[7]));
    float fy = (sy[0] + sy[1]) + (sy[2] + sy[3]) + ((sy[4] + sy[5]) + (sy[6] + sy[7]));
    float* zp = g_zp + ((size_t)(b * (HW / ZROWBLK) + blockIdx.y)) * HW
              + (size_t)(blockIdx.x * 256 + t) * 2;
    zp[0] = fx; zp[1] = fy;
}

// ------- stage 2: combine partials, reciprocal -------------------------------
__global__ void zfin_kernel() {
    int idx = blockIdx.x * 256 + threadIdx.x;   // < BATCH*HW
    int b = idx >> 12, i = idx & (HW - 1);
    const float* zp = g_zp + (size_t)b * (HW / ZROWBLK) * HW + i;
    float s0 = 0.f, s1 = 0.f, s2 = 0.f, s3 = 0.f;
    #pragma unroll
    for (int p = 0; p < HW / ZROWBLK; p += 4) {
        s0 += zp[(size_t)(p + 0) * HW];
        s1 += zp[(size_t)(p + 1) * HW];
        s2 += zp[(size_t)(p + 2) * HW];
        s3 += zp[(size_t)(p + 3) * HW];
    }
    g_z[idx] = 1.f / ((s0 + s1) + (s2 + s3));
}

// ------- V-hat: g_vb[c][i] = bf16(g_vt[c][i] * g_z[i]) -----------------------
__global__ void vscale_kernel() {
    size_t idx4 = (size_t)blockIdx.x * 256 + threadIdx.x;
    int b = (int)(idx4 / ((size_t)CCH * (HW / 4)));
    size_t rem = idx4 - (size_t)b * CCH * (HW / 4);
    int i4 = (int)(rem % (HW / 4));
    float4 v = ((const float4*)g_vt)[idx4];
    float4 z = ((const float4*)g_z)[(size_t)b * (HW / 4) + i4];
    __nv_bfloat162* o = ((__nv_bfloat162*)g_vb) + idx4 * 2;
    o[0] = __floats2bfloat162_rn(v.x * z.x, v.y * z.y);
    o[1] = __floats2bfloat162_rn(v.z * z.z, v.w * z.w);
}

// ------ O GEMM (bf16): O[j,c] = sum_i E'[j,i] * Vhat[c,i] -> bf16 ------------
__global__ __launch_bounds__(256, 2)
void o_bf16_kernel() {
    extern __shared__ unsigned osm[];
    int b = blockIdx.z;
    const __nv_bfloat16* Ag = g_s  + (size_t)b * HW * HW + (size_t)(blockIdx.x * 128) * HW;
    const __nv_bfloat16* Bg = g_vb + (size_t)b * CCH * HW + (size_t)(blockIdx.y * 128) * HW;
    uint32_t sbase = sptr(osm);
    BF16_PREAMBLE();

    const int NC = HW / 32;
    #pragma unroll
    for (int s = 0; s < 2; s++) {
        BF16_LOAD_STAGE(sbase + s * O_STG_BYTES, Ag, HW, Bg, HW, s);
        CPCOMMIT();
    }
    for (int kt = 0; kt < NC; kt++) {
        CPWAIT1();
        __syncthreads();
        uint32_t At_s = sbase + (kt % 3) * O_STG_BYTES;
        uint32_t Bt_s = At_s + 10240;
        BF16_CHUNK_MMAS(acc, At_s, Bt_s);
        int nk = kt + 2;
        if (nk < NC) {
            BF16_LOAD_STAGE(sbase + (nk % 3) * O_STG_BYTES, Ag, HW, Bg, HW, nk);
        }
        CPCOMMIT();
    }
    __nv_bfloat16* Cp = g_ob + (size_t)b * HW * CCH;
    int m0 = blockIdx.x * 128, n0 = blockIdx.y * 128;
    #pragma unroll
    for (int mi = 0; mi < 4; mi++)
        #pragma unroll
        for (int nj = 0; nj < 4; nj++) {
            int r = m0 + wm + mi * 16 + g;
            int c = n0 + wn + nj * 8 + 2 * tig;
            *(__nv_bfloat162*)&Cp[(size_t)r * CCH + c] =
                __floats2bfloat162_rn(acc[mi][nj][0], acc[mi][nj][1]);
            *(__nv_bfloat162*)&Cp[(size_t)(r + 8) * CCH + c] =
                __floats2bfloat162_rn(acc[mi][nj][2], acc[mi][nj][3]);
        }
}

// ------ Proj+residual (bf16): out[o,m] = x[o,m] + sum_c O[m,c]Wp[o,c]+bp[o] --
__global__ __launch_bounds__(256, 2)
void proj_bf16_kernel(const float* __restrict__ bp,
                      const float* __restrict__ x, float* __restrict__ out) {
    extern __shared__ unsigned ssm[];
    int b = blockIdx.z;
    int n0 = blockIdx.y * 128, m0 = blockIdx.x * 128;
    const __nv_bfloat16* Ag = g_ob + (size_t)b * HW * CCH + (size_t)m0 * CCH;
    const __nv_bfloat16* Bg = g_wb + (size_t)3 * CCH * CCH + (size_t)n0 * CCH;
    const float* xb = x   + (size_t)b * CCH * HW;
    float* ob = out + (size_t)b * CCH * HW;
    uint32_t sbase = sptr(ssm);
    BF16_PREAMBLE();

    const int NC = CCH / 32;   // 16
    #pragma unroll
    for (int s = 0; s < 2; s++) {
        BF16_LOAD_STAGE(sbase + s * O_STG_BYTES, Ag, CCH, Bg, CCH, s);
        CPCOMMIT();
    }
    for (int kt = 0; kt < NC; kt++) {
        CPWAIT1();
        __syncthreads();
        uint32_t At_s = sbase + (kt % 3) * O_STG_BYTES;
        uint32_t Bt_s = At_s + 10240;
        BF16_CHUNK_MMAS(acc, At_s, Bt_s);
        int nk = kt + 2;
        if (nk < NC) {
            BF16_LOAD_STAGE(sbase + (nk % 3) * O_STG_BYTES, Ag, CCH, Bg, CCH, nk);
        }
        CPCOMMIT();
    }
    #pragma unroll
    for (int nj = 0; nj < 4; nj++) {
        int c0 = n0 + wn + nj * 8 + 2 * tig;
        float bv0 = bp[c0], bv1 = bp[c0 + 1];
        #pragma unroll
        for (int mi = 0; mi < 4; mi++) {
            int r = m0 + wm + mi * 16 + g;
            ob[(size_t)c0 * HW + r]           = xb[(size_t)c0 * HW + r]           + acc[mi][nj][0] + bv0;
            ob[(size_t)(c0 + 1) * HW + r]     = xb[(size_t)(c0 + 1) * HW + r]     + acc[mi][nj][1] + bv1;
            ob[(size_t)c0 * HW + r + 8]       = xb[(size_t)c0 * HW + r + 8]       + acc[mi][nj][2] + bv0;
            ob[(size_t)(c0 + 1) * HW + r + 8] = xb[(size_t)(c0 + 1) * HW + r + 8] + acc[mi][nj][3] + bv1;
        }
    }
}

// ------------------------------ launch ---------------------------------------
extern "C" void kernel_launch(void* const* d_in, const int* in_sizes, int n_in,
                              void* d_out, int out_size) {
    const float* x  = (const float*)d_in[0];
    const float* nw = (const float*)d_in[1];
    const float* nb = (const float*)d_in[2];
    const float* wq = (const float*)d_in[3];
    const float* bq = (const float*)d_in[4];
    const float* wk = (const float*)d_in[5];
    const float* bk = (const float*)d_in[6];
    const float* wv = (const float*)d_in[7];
    const float* bv = (const float*)d_in[8];
    const float* wp = (const float*)d_in[9];
    const float* bp = (const float*)d_in[10];
    float* out = (float*)d_out;

    static int attr_done = 0;
    if (!attr_done) {
        cudaFuncSetAttribute(qkv_bf16_kernel,
                             cudaFuncAttributeMaxDynamicSharedMemorySize, O_DYN_B);
        cudaFuncSetAttribute(scores_bf16_kernel,
                             cudaFuncAttributeMaxDynamicSharedMemorySize, O_DYN_B);
        cudaFuncSetAttribute(o_bf16_kernel,
                             cudaFuncAttributeMaxDynamicSharedMemorySize, O_DYN_B);
        cudaFuncSetAttribute(proj_bf16_kernel,
                             cudaFuncAttributeMaxDynamicSharedMemorySize, O_DYN_B);
        attr_done = 1;
    }

    groupnorm_kernel<<<BATCH * NGRP, 256>>>(x, nw, nb);

    wcvt_kernel<<<(4 * CCH * CCH / 4) / 256, 256>>>(wq, wk, wv, wp);

    dim3 gtr(HW / 32, CCH / 32, BATCH);         // 128 x 16 x 2
    hb_transpose_kernel<<<gtr, 256>>>();

    dim3 gqkv(HW / 128, 3 * CCH / 128, BATCH);  // 32 x 12 x 2
    qkv_bf16_kernel<<<gqkv, 256, O_DYN_B>>>(bq, bk, bv);

    dim3 gsc(HW / 128, HW / 128, BATCH);        // 32 x 32 x 2
    scores_bf16_kernel<<<gsc, 256, O_DYN_B>>>();

    dim3 gzc(HW / 512, HW / ZROWBLK, BATCH);    // 8 x 64 x 2
    zcolsum_kernel<<<gzc, 256>>>();
    zfin_kernel<<<(BATCH * HW) / 256, 256>>>();
    vscale_kernel<<<(BATCH * CCH * HW) / (4 * 256), 256>>>();

    dim3 go(HW / 128, CCH / 128, BATCH);        // 32 x 4 x 2
    o_bf16_kernel<<<go, 256, O_DYN_B>>>();

    proj_bf16_kernel<<<go, 256, O_DYN_B>>>(bp, x, out);
}

// round 16
// speedup vs baseline: 1.9188x; 1.0433x over previous
#include <cuda_runtime.h>
#include <cuda_bf16.h>
#include <math.h>
#include <float.h>
#include <stdint.h>

#define BATCH 2
#define CCH   512
#define HW    4096
#define NGRP  32
#define CPG   16
#define GRPELEM (CPG * HW)   // 65536

// bf16 GEMM geometry: CTA tile 128(M) x 256(N), k-chunk 32, 80 B padded rows
#define OROWW 20
#define ASTG_B (128 * 80)              // 10240
#define BSTG_B (256 * 80)              // 20480
#define STG_B  (ASTG_B + BSTG_B)       // 30720
#define DYN_B  (3 * STG_B)             // 92160

#define ZROWBLK 64   // rows per zcolsum CTA

// ---------------- scratch (static device globals; no allocation) -------------
__device__ float         g_hn  [(size_t)BATCH * CCH * HW];  // normed [b][c][n] fp32
__device__ __nv_bfloat16 g_hb  [(size_t)BATCH * HW * CCH];  // normed [b][n][c] bf16
__device__ __nv_bfloat16 g_wb  [4 * (size_t)CCH * CCH];     // wq,wk,wv,wp bf16
__device__ __nv_bfloat16 g_q   [(size_t)BATCH * HW * CCH];  // [b][i][c] bf16
__device__ __nv_bfloat16 g_k   [(size_t)BATCH * HW * CCH];  // [b][j][c] bf16
__device__ float         g_vt  [(size_t)BATCH * CCH * HW];  // [b][c][i] fp32
__device__ __nv_bfloat16 g_vb  [(size_t)BATCH * CCH * HW];  // [b][c][i] bf16 * 1/Z_i
__device__ __nv_bfloat16 g_s   [(size_t)BATCH * HW * HW];   // E'[j][i] = exp(scale*S^T)
__device__ __nv_bfloat16 g_ob  [(size_t)BATCH * HW * CCH];  // attn out [b][j][c] bf16
__device__ float         g_zp  [(size_t)BATCH * (HW / ZROWBLK) * HW]; // partials
__device__ float         g_z   [(size_t)BATCH * HW];        // 1/Z_i

// ------------------------------ helpers --------------------------------------
__device__ __forceinline__ void mma16(float* d, const unsigned* a, const unsigned* b) {
    asm volatile(
        "mma.sync.aligned.m16n8k16.row.col.f32.bf16.bf16.f32 "
        "{%0,%1,%2,%3}, {%4,%5,%6,%7}, {%8,%9}, {%0,%1,%2,%3};\n"
        : "+f"(d[0]), "+f"(d[1]), "+f"(d[2]), "+f"(d[3])
        : "r"(a[0]), "r"(a[1]), "r"(a[2]), "r"(a[3]), "r"(b[0]), "r"(b[1]));
}
__device__ __forceinline__ void ldsm4(unsigned* r, uint32_t addr) {
    asm volatile(
        "ldmatrix.sync.aligned.m8n8.x4.shared.b16 {%0,%1,%2,%3}, [%4];"
        : "=r"(r[0]), "=r"(r[1]), "=r"(r[2]), "=r"(r[3]) : "r"(addr));
}
__device__ __forceinline__ unsigned sptr(const void* p) {
    return (unsigned)__cvta_generic_to_shared(p);
}
#define CPA16(dst, src) asm volatile("cp.async.ca.shared.global [%0], [%1], 16;\n" :: "r"(dst), "l"(src))
#define CPCOMMIT()      asm volatile("cp.async.commit_group;\n")
#define CPWAIT1()       asm volatile("cp.async.wait_group 1;\n" ::: "memory")

// ---------------------------- GroupNorm --------------------------------------
__global__ void groupnorm_kernel(const float* __restrict__ x,
                                 const float* __restrict__ gw,
                                 const float* __restrict__ gb) {
    int b = blockIdx.x >> 5;
    int g = blockIdx.x & 31;
    const float4* xp = (const float4*)(x    + ((size_t)b * CCH + g * CPG) * HW);
    float4*       op = (float4*)      (g_hn + ((size_t)b * CCH + g * CPG) * HW);
    int tid = threadIdx.x;

    float s = 0.f, ss = 0.f;
    for (int i = tid; i < GRPELEM / 4; i += 256) {
        float4 v = xp[i];
        s  += v.x + v.y + v.z + v.w;
        ss += v.x * v.x + v.y * v.y + v.z * v.z + v.w * v.w;
    }
    __shared__ float shs[8], shss[8];
    #pragma unroll
    for (int o = 16; o; o >>= 1) {
        s  += __shfl_xor_sync(0xffffffffu, s,  o);
        ss += __shfl_xor_sync(0xffffffffu, ss, o);
    }
    if ((tid & 31) == 0) { shs[tid >> 5] = s; shss[tid >> 5] = ss; }
    __syncthreads();
    __shared__ float sm, sr;
    if (tid == 0) {
        float S = 0.f, SS = 0.f;
        #pragma unroll
        for (int i = 0; i < 8; i++) { S += shs[i]; SS += shss[i]; }
        float mean = S / (float)GRPELEM;
        float var  = SS / (float)GRPELEM - mean * mean;
        sm = mean;
        sr = rsqrtf(var + 1e-6f);
    }
    __syncthreads();
    float mean = sm, rstd = sr;
    for (int i = tid; i < GRPELEM / 4; i += 256) {
        int cl = i >> 10;
        float sc = gw[g * CPG + cl] * rstd;
        float sh = gb[g * CPG + cl] - mean * sc;
        float4 v = xp[i];
        v.x = v.x * sc + sh; v.y = v.y * sc + sh;
        v.z = v.z * sc + sh; v.w = v.w * sc + sh;
        op[i] = v;
    }
}

// ------- transpose normed activations: g_hn [c][n] fp32 -> g_hb [n][c] bf16 --
__global__ void hb_transpose_kernel() {
    __shared__ float tile[32][33];
    int b = blockIdx.z;
    int c0 = blockIdx.y * 32, n0 = blockIdx.x * 32;
    int tx = threadIdx.x & 31, ty = threadIdx.x >> 5;   // 256 thr: ty 0..7
    const float* src = g_hn + ((size_t)b * CCH + c0) * HW + n0;
    #pragma unroll
    for (int r = ty; r < 32; r += 8)
        tile[r][tx] = src[(size_t)r * HW + tx];
    __syncthreads();
    __nv_bfloat16* dst = g_hb + ((size_t)b * HW + n0) * CCH + c0;
    #pragma unroll
    for (int r = ty; r < 32; r += 8)
        dst[(size_t)r * CCH + tx] = __float2bfloat16(tile[tx][r]);
}

// ------- convert weights to bf16: g_wb[which] = bf16(w) ----------------------
__global__ void wcvt_kernel(const float* __restrict__ wq, const float* __restrict__ wk,
                            const float* __restrict__ wv, const float* __restrict__ wp) {
    int idx = blockIdx.x * 256 + threadIdx.x;         // float4 index
    int which = idx / (CCH * CCH / 4);
    int off   = idx % (CCH * CCH / 4);
    const float* src = which == 0 ? wq : which == 1 ? wk : which == 2 ? wv : wp;
    float4 v = ((const float4*)src)[off];
    __nv_bfloat162* d = (__nv_bfloat162*)(g_wb + (size_t)which * CCH * CCH) + off * 2;
    d[0] = __floats2bfloat162_rn(v.x, v.y);
    d[1] = __floats2bfloat162_rn(v.z, v.w);
}

// ---- bf16 mainloop body: warp tile 64x64, ldmatrix frags --------------------
#define BF16_CHUNK_MMAS(acc, At_s, Bt_s)  do {                                 \
    _Pragma("unroll")                                                          \
    for (int kk = 0; kk < 2; kk++) {                                           \
        unsigned af[4][4], bf[8][2];                                           \
        _Pragma("unroll")                                                      \
        for (int mi = 0; mi < 4; mi++)                                         \
            ldsm4(af[mi], (At_s) +                                             \
                  4u * ((wm + mi * 16 + a_row) * OROWW + kk * 8 + a_kw));      \
        _Pragma("unroll")                                                      \
        for (int njp = 0; njp < 4; njp++)                                      \
            ldsm4(&bf[2 * njp][0], (Bt_s) +                                    \
                  4u * ((wn + njp * 16 + b_row) * OROWW + kk * 8 + b_kw));     \
        _Pragma("unroll")                                                      \
        for (int mi = 0; mi < 4; mi++)                                         \
            _Pragma("unroll")                                                  \
            for (int nj = 0; nj < 8; nj++) mma16((acc)[mi][nj], af[mi], bf[nj]); \
    } } while (0)

// A tile: 128 rows; B tile: 256 rows (each 32 bf16 = 64 B, padded 80 B)
#define BF16_LOAD_STAGE(st, Ag, Astr, Bg, Bstr, ck) do {                       \
    const __nv_bfloat16* as = (Ag) + (size_t)lrow * (Astr) + (ck) * 32 + lh * 16; \
    CPA16((st) + lrow * 80 + lh * 32,      as);                                \
    CPA16((st) + lrow * 80 + lh * 32 + 16, as + 8);                            \
    _Pragma("unroll")                                                          \
    for (int rr = 0; rr < 2; rr++) {                                           \
        int brr = lrow + rr * 128;                                             \
        const __nv_bfloat16* bs = (Bg) + (size_t)brr * (Bstr) + (ck) * 32 + lh * 16; \
        CPA16((st) + ASTG_B + brr * 80 + lh * 32,      bs);                    \
        CPA16((st) + ASTG_B + brr * 80 + lh * 32 + 16, bs + 8);                \
    } } while (0)

#define BF16_PREAMBLE()                                                        \
    int tid = threadIdx.x;                                                     \
    int lane = tid & 31, warp = tid >> 5;                                      \
    int g = lane >> 2, tig = lane & 3;                                         \
    int wm = (warp >> 2) * 64, wn = (warp & 3) * 64;                           \
    int lrow = tid >> 1, lh = tid & 1;                                         \
    int mat = lane >> 3, mr = lane & 7;                                        \
    int a_row = ((mat & 1) << 3) + mr, a_kw = (mat >> 1) << 2;                 \
    int b_row = ((mat >> 1) << 3) + mr, b_kw = (mat & 1) << 2;                 \
    (void)g; (void)tig;                                                        \
    float acc[4][8][4];                                                        \
    _Pragma("unroll")                                                          \
    for (int i = 0; i < 4; i++)                                                \
        _Pragma("unroll")                                                      \
        for (int j = 0; j < 8; j++)                                            \
            _Pragma("unroll")                                                  \
            for (int t = 0; t < 4; t++) acc[i][j][t] = 0.f;

// -------- QKV GEMM (bf16, merged): C[m,n] = sum_c Hb[m,c]*W[n,c] + bias[n] ---
// which 0 -> g_q bf16 [i][c], 1 -> g_k bf16 [j][c], 2 -> g_vt fp32 [c][i]
__global__ __launch_bounds__(256, 1)
void qkv_bf16_kernel(const float* __restrict__ bq, const float* __restrict__ bk,
                     const float* __restrict__ bv) {
    extern __shared__ unsigned ssm[];
    int b = blockIdx.z;
    int which = blockIdx.y >> 1;
    int n0 = (blockIdx.y & 1) * 256, m0 = blockIdx.x * 128;
    const __nv_bfloat16* Ag = g_hb + (size_t)b * HW * CCH + (size_t)m0 * CCH;
    const __nv_bfloat16* Bg = g_wb + (size_t)which * CCH * CCH + (size_t)n0 * CCH;
    const float* bias = which == 0 ? bq : which == 1 ? bk : bv;
    uint32_t sbase = sptr(ssm);
    BF16_PREAMBLE();

    const int NC = CCH / 32;   // 16
    #pragma unroll
    for (int s = 0; s < 2; s++) {
        BF16_LOAD_STAGE(sbase + s * STG_B, Ag, CCH, Bg, CCH, s);
        CPCOMMIT();
    }
    for (int kt = 0; kt < NC; kt++) {
        CPWAIT1();
        __syncthreads();
        uint32_t At_s = sbase + (kt % 3) * STG_B;
        uint32_t Bt_s = At_s + ASTG_B;
        BF16_CHUNK_MMAS(acc, At_s, Bt_s);
        int nk = kt + 2;
        if (nk < NC) {
            BF16_LOAD_STAGE(sbase + (nk % 3) * STG_B, Ag, CCH, Bg, CCH, nk);
        }
        CPCOMMIT();
    }
    if (which == 2) {
        float* Vt = g_vt + (size_t)b * CCH * HW;
        #pragma unroll
        for (int mi = 0; mi < 4; mi++)
            #pragma unroll
            for (int nj = 0; nj < 8; nj++) {
                int r = m0 + wm + mi * 16 + g;
                int c = n0 + wn + nj * 8 + 2 * tig;
                float bv0 = bias[c], bv1 = bias[c + 1];
                Vt[(size_t)c * HW + r]           = acc[mi][nj][0] + bv0;
                Vt[(size_t)(c + 1) * HW + r]     = acc[mi][nj][1] + bv1;
                Vt[(size_t)c * HW + r + 8]       = acc[mi][nj][2] + bv0;
                Vt[(size_t)(c + 1) * HW + r + 8] = acc[mi][nj][3] + bv1;
            }
    } else {
        __nv_bfloat16* Cp = (which == 0 ? g_q : g_k) + (size_t)b * HW * CCH;
        #pragma unroll
        for (int mi = 0; mi < 4; mi++)
            #pragma unroll
            for (int nj = 0; nj < 8; nj++) {
                int r = m0 + wm + mi * 16 + g;
                int c = n0 + wn + nj * 8 + 2 * tig;
                float bv0 = bias[c], bv1 = bias[c + 1];
                *(__nv_bfloat162*)&Cp[(size_t)r * CCH + c] =
                    __floats2bfloat162_rn(acc[mi][nj][0] + bv0, acc[mi][nj][1] + bv1);
                *(__nv_bfloat162*)&Cp[(size_t)(r + 8) * CCH + c] =
                    __floats2bfloat162_rn(acc[mi][nj][2] + bv0, acc[mi][nj][3] + bv1);
            }
    }
}

// -------- Scores (bf16): E'[j,i] = exp(scale * K_j . Q_i) -> bf16 ------------
__global__ __launch_bounds__(256, 1)
void scores_bf16_kernel() {
    extern __shared__ unsigned ssm[];
    int b = blockIdx.z;
    const __nv_bfloat16* Ag = g_k + (size_t)b * HW * CCH + (size_t)(blockIdx.x * 128) * CCH;
    const __nv_bfloat16* Bg = g_q + (size_t)b * HW * CCH + (size_t)(blockIdx.y * 256) * CCH;
    uint32_t sbase = sptr(ssm);
    BF16_PREAMBLE();

    const int NC = CCH / 32;   // 16
    #pragma unroll
    for (int s = 0; s < 2; s++) {
        BF16_LOAD_STAGE(sbase + s * STG_B, Ag, CCH, Bg, CCH, s);
        CPCOMMIT();
    }
    for (int kt = 0; kt < NC; kt++) {
        CPWAIT1();
        __syncthreads();
        uint32_t At_s = sbase + (kt % 3) * STG_B;
        uint32_t Bt_s = At_s + ASTG_B;
        BF16_CHUNK_MMAS(acc, At_s, Bt_s);
        int nk = kt + 2;
        if (nk < NC) {
            BF16_LOAD_STAGE(sbase + (nk % 3) * STG_B, Ag, CCH, Bg, CCH, nk);
        }
        CPCOMMIT();
    }
    const float scale = 0.04419417382415922f;   // 512^-0.5
    __nv_bfloat16* Cp = g_s + (size_t)b * HW * HW;
    int m0 = blockIdx.x * 128, n0 = blockIdx.y * 256;
    #pragma unroll
    for (int mi = 0; mi < 4; mi++)
        #pragma unroll
        for (int nj = 0; nj < 8; nj++) {
            int r = m0 + wm + mi * 16 + g;
            int c = n0 + wn + nj * 8 + 2 * tig;
            *(__nv_bfloat162*)&Cp[(size_t)r * HW + c] =
                __floats2bfloat162_rn(__expf(acc[mi][nj][0] * scale),
                                      __expf(acc[mi][nj][1] * scale));
            *(__nv_bfloat162*)&Cp[(size_t)(r + 8) * HW + c] =
                __floats2bfloat162_rn(__expf(acc[mi][nj][2] * scale),
                                      __expf(acc[mi][nj][3] * scale));
        }
}

// ------- column sums of E' stage 1: each CTA sums 64 rows x 512 cols ---------
__global__ void zcolsum_kernel() {
    int b = blockIdx.z;
    const __nv_bfloat162* S = (const __nv_bfloat162*)(g_s + (size_t)b * HW * HW);
    int t = threadIdx.x;
    size_t rowstride = HW / 2;
    const __nv_bfloat162* p = S + (size_t)(blockIdx.y * ZROWBLK) * rowstride
                                + blockIdx.x * 256 + t;
    float sx[8], sy[8];
    #pragma unroll
    for (int u = 0; u < 8; u++) { sx[u] = 0.f; sy[u] = 0.f; }
    #pragma unroll
    for (int jj = 0; jj < ZROWBLK / 8; jj++) {
        #pragma unroll
        for (int u = 0; u < 8; u++) {
            float2 v = __bfloat1622float2(p[(size_t)(jj * 8 + u) * rowstride]);
            sx[u] += v.x; sy[u] += v.y;
        }
    }
    float fx = (sx[0] + sx[1]) + (sx[2] + sx[3]) + ((sx[4] + sx[5]) + (sx[6] + sx[7]));
    float fy = (sy[0] + sy[1]) + (sy[2] + sy[3]) + ((sy[4] + sy[5]) + (sy[6] + sy[7]));
    float* zp = g_zp + ((size_t)(b * (HW / ZROWBLK) + blockIdx.y)) * HW
              + (size_t)(blockIdx.x * 256 + t) * 2;
    zp[0] = fx; zp[1] = fy;
}

// ------- stage 2: combine partials, reciprocal -------------------------------
__global__ void zfin_kernel() {
    int idx = blockIdx.x * 256 + threadIdx.x;   // < BATCH*HW
    int b = idx >> 12, i = idx & (HW - 1);
    const float* zp = g_zp + (size_t)b * (HW / ZROWBLK) * HW + i;
    float s0 = 0.f, s1 = 0.f, s2 = 0.f, s3 = 0.f;
    #pragma unroll
    for (int p = 0; p < HW / ZROWBLK; p += 4) {
        s0 += zp[(size_t)(p + 0) * HW];
        s1 += zp[(size_t)(p + 1) * HW];
        s2 += zp[(size_t)(p + 2) * HW];
        s3 += zp[(size_t)(p + 3) * HW];
    }
    g_z[idx] = 1.f / ((s0 + s1) + (s2 + s3));
}

// ------- V-hat: g_vb[c][i] = bf16(g_vt[c][i] * g_z[i]) -----------------------
__global__ void vscale_kernel() {
    size_t idx4 = (size_t)blockIdx.x * 256 + threadIdx.x;
    int b = (int)(idx4 / ((size_t)CCH * (HW / 4)));
    size_t rem = idx4 - (size_t)b * CCH * (HW / 4);
    int i4 = (int)(rem % (HW / 4));
    float4 v = ((const float4*)g_vt)[idx4];
    float4 z = ((const float4*)g_z)[(size_t)b * (HW / 4) + i4];
    __nv_bfloat162* o = ((__nv_bfloat162*)g_vb) + idx4 * 2;
    o[0] = __floats2bfloat162_rn(v.x * z.x, v.y * z.y);
    o[1] = __floats2bfloat162_rn(v.z * z.z, v.w * z.w);
}

// ------ O GEMM (bf16): O[j,c] = sum_i E'[j,i] * Vhat[c,i] -> bf16 ------------
__global__ __launch_bounds__(256, 1)
void o_bf16_kernel() {
    extern __shared__ unsigned osm[];
    int b = blockIdx.z;
    const __nv_bfloat16* Ag = g_s  + (size_t)b * HW * HW + (size_t)(blockIdx.x * 128) * HW;
    const __nv_bfloat16* Bg = g_vb + (size_t)b * CCH * HW + (size_t)(blockIdx.y * 256) * HW;
    uint32_t sbase = sptr(osm);
    BF16_PREAMBLE();

    const int NC = HW / 32;
    #pragma unroll
    for (int s = 0; s < 2; s++) {
        BF16_LOAD_STAGE(sbase + s * STG_B, Ag, HW, Bg, HW, s);
        CPCOMMIT();
    }
    for (int kt = 0; kt < NC; kt++) {
        CPWAIT1();
        __syncthreads();
        uint32_t At_s = sbase + (kt % 3) * STG_B;
        uint32_t Bt_s = At_s + ASTG_B;
        BF16_CHUNK_MMAS(acc, At_s, Bt_s);
        int nk = kt + 2;
        if (nk < NC) {
            BF16_LOAD_STAGE(sbase + (nk % 3) * STG_B, Ag, HW, Bg, HW, nk);
        }
        CPCOMMIT();
    }
    __nv_bfloat16* Cp = g_ob + (size_t)b * HW * CCH;
    int m0 = blockIdx.x * 128, n0 = blockIdx.y * 256;
    #pragma unroll
    for (int mi = 0; mi < 4; mi++)
        #pragma unroll
        for (int nj = 0; nj < 8; nj++) {
            int r = m0 + wm + mi * 16 + g;
            int c = n0 + wn + nj * 8 + 2 * tig;
            *(__nv_bfloat162*)&Cp[(size_t)r * CCH + c] =
                __floats2bfloat162_rn(acc[mi][nj][0], acc[mi][nj][1]);
            *(__nv_bfloat162*)&Cp[(size_t)(r + 8) * CCH + c] =
                __floats2bfloat162_rn(acc[mi][nj][2], acc[mi][nj][3]);
        }
}

// ------ Proj+residual (bf16): out[o,m] = x[o,m] + sum_c O[m,c]Wp[o,c]+bp[o] --
__global__ __launch_bounds__(256, 1)
void proj_bf16_kernel(const float* __restrict__ bp,
                      const float* __restrict__ x, float* __restrict__ out) {
    extern __shared__ unsigned ssm[];
    int b = blockIdx.z;
    int n0 = blockIdx.y * 256, m0 = blockIdx.x * 128;
    const __nv_bfloat16* Ag = g_ob + (size_t)b * HW * CCH + (size_t)m0 * CCH;
    const __nv_bfloat16* Bg = g_wb + (size_t)3 * CCH * CCH + (size_t)n0 * CCH;
    const float* xb = x   + (size_t)b * CCH * HW;
    float* ob = out + (size_t)b * CCH * HW;
    uint32_t sbase = sptr(ssm);
    BF16_PREAMBLE();

    const int NC = CCH / 32;   // 16
    #pragma unroll
    for (int s = 0; s < 2; s++) {
        BF16_LOAD_STAGE(sbase + s * STG_B, Ag, CCH, Bg, CCH, s);
        CPCOMMIT();
    }
    for (int kt = 0; kt < NC; kt++) {
        CPWAIT1();
        __syncthreads();
        uint32_t At_s = sbase + (kt % 3) * STG_B;
        uint32_t Bt_s = At_s + ASTG_B;
        BF16_CHUNK_MMAS(acc, At_s, Bt_s);
        int nk = kt + 2;
        if (nk < NC) {
            BF16_LOAD_STAGE(sbase + (nk % 3) * STG_B, Ag, CCH, Bg, CCH, nk);
        }
        CPCOMMIT();
    }
    #pragma unroll
    for (int nj = 0; nj < 8; nj++) {
        int c0 = n0 + wn + nj * 8 + 2 * tig;
        float bv0 = bp[c0], bv1 = bp[c0 + 1];
        #pragma unroll
        for (int mi = 0; mi < 4; mi++) {
            int r = m0 + wm + mi * 16 + g;
            ob[(size_t)c0 * HW + r]           = xb[(size_t)c0 * HW + r]           + acc[mi][nj][0] + bv0;
            ob[(size_t)(c0 + 1) * HW + r]     = xb[(size_t)(c0 + 1) * HW + r]     + acc[mi][nj][1] + bv1;
            ob[(size_t)c0 * HW + r + 8]       = xb[(size_t)c0 * HW + r + 8]       + acc[mi][nj][2] + bv0;
            ob[(size_t)(c0 + 1) * HW + r + 8] = xb[(size_t)(c0 + 1) * HW + r + 8] + acc[mi][nj][3] + bv1;
        }
    }
}

// ------------------------------ launch ---------------------------------------
extern "C" void kernel_launch(void* const* d_in, const int* in_sizes, int n_in,
                              void* d_out, int out_size) {
    const float* x  = (const float*)d_in[0];
    const float* nw = (const float*)d_in[1];
    const float* nb = (const float*)d_in[2];
    const float* wq = (const float*)d_in[3];
    const float* bq = (const float*)d_in[4];
    const float* wk = (const float*)d_in[5];
    const float* bk = (const float*)d_in[6];
    const float* wv = (const float*)d_in[7];
    const float* bv = (const float*)d_in[8];
    const float* wp = (const float*)d_in[9];
    const float* bp = (const float*)d_in[10];
    float* out = (float*)d_out;

    static int attr_done = 0;
    if (!attr_done) {
        cudaFuncSetAttribute(qkv_bf16_kernel,
                             cudaFuncAttributeMaxDynamicSharedMemorySize, DYN_B);
        cudaFuncSetAttribute(scores_bf16_kernel,
                             cudaFuncAttributeMaxDynamicSharedMemorySize, DYN_B);
        cudaFuncSetAttribute(o_bf16_kernel,
                             cudaFuncAttributeMaxDynamicSharedMemorySize, DYN_B);
        cudaFuncSetAttribute(proj_bf16_kernel,
                             cudaFuncAttributeMaxDynamicSharedMemorySize, DYN_B);
        attr_done = 1;
    }

    groupnorm_kernel<<<BATCH * NGRP, 256>>>(x, nw, nb);

    wcvt_kernel<<<(4 * CCH * CCH / 4) / 256, 256>>>(wq, wk, wv, wp);

    dim3 gtr(HW / 32, CCH / 32, BATCH);         // 128 x 16 x 2
    hb_transpose_kernel<<<gtr, 256>>>();

    dim3 gqkv(HW / 128, 3 * CCH / 256, BATCH);  // 32 x 6 x 2
    qkv_bf16_kernel<<<gqkv, 256, DYN_B>>>(bq, bk, bv);

    dim3 gsc(HW / 128, HW / 256, BATCH);        // 32 x 16 x 2
    scores_bf16_kernel<<<gsc, 256, DYN_B>>>();

    dim3 gzc(HW / 512, HW / ZROWBLK, BATCH);    // 8 x 64 x 2
    zcolsum_kernel<<<gzc, 256>>>();
    zfin_kernel<<<(BATCH * HW) / 256, 256>>>();
    vscale_kernel<<<(BATCH * CCH * HW) / (4 * 256), 256>>>();

    dim3 go(HW / 128, CCH / 256, BATCH);        // 32 x 2 x 2
    o_bf16_kernel<<<go, 256, DYN_B>>>();

    proj_bf16_kernel<<<go, 256, DYN_B>>>(bp, x, out);
}

// round 17
// speedup vs baseline: 2.1039x; 1.0965x over previous
#include <cuda_runtime.h>
#include <cuda_bf16.h>
#include <math.h>
#include <float.h>
#include <stdint.h>

#define BATCH 2
#define CCH   512
#define HW    4096
#define NGRP  32
#define CPG   16
#define GRPELEM (CPG * HW)   // 65536

// bf16 GEMM geometry: CTA tile 128(M) x 256(N), k-chunk 64, 144 B padded rows
#define OROWW 36                       // words per row (128 B data + 16 B pad)
#define ASTG_B (128 * 144)             // 18432
#define BSTG_B (256 * 144)             // 36864
#define STG_B  (ASTG_B + BSTG_B)       // 55296
#define DYN_B  (3 * STG_B)             // 165888

#define ZROWBLK 64   // rows per zcolsum CTA

// ---------------- scratch (static device globals; no allocation) -------------
__device__ float         g_hn  [(size_t)BATCH * CCH * HW];  // normed [b][c][n] fp32
__device__ __nv_bfloat16 g_hb  [(size_t)BATCH * HW * CCH];  // normed [b][n][c] bf16
__device__ __nv_bfloat16 g_wb  [4 * (size_t)CCH * CCH];     // wq,wk,wv,wp bf16
__device__ __nv_bfloat16 g_q   [(size_t)BATCH * HW * CCH];  // [b][i][c] bf16
__device__ __nv_bfloat16 g_k   [(size_t)BATCH * HW * CCH];  // [b][j][c] bf16
__device__ float         g_vt  [(size_t)BATCH * CCH * HW];  // [b][c][i] fp32
__device__ __nv_bfloat16 g_vb  [(size_t)BATCH * CCH * HW];  // [b][c][i] bf16 * 1/Z_i
__device__ __nv_bfloat16 g_s   [(size_t)BATCH * HW * HW];   // E'[j][i] = exp(scale*S^T)
__device__ __nv_bfloat16 g_ob  [(size_t)BATCH * HW * CCH];  // attn out [b][j][c] bf16
__device__ float         g_zp  [(size_t)BATCH * (HW / ZROWBLK) * HW]; // partials
__device__ float         g_z   [(size_t)BATCH * HW];        // 1/Z_i

// ------------------------------ helpers --------------------------------------
__device__ __forceinline__ void mma16(float* d, const unsigned* a, const unsigned* b) {
    asm volatile(
        "mma.sync.aligned.m16n8k16.row.col.f32.bf16.bf16.f32 "
        "{%0,%1,%2,%3}, {%4,%5,%6,%7}, {%8,%9}, {%0,%1,%2,%3};\n"
        : "+f"(d[0]), "+f"(d[1]), "+f"(d[2]), "+f"(d[3])
        : "r"(a[0]), "r"(a[1]), "r"(a[2]), "r"(a[3]), "r"(b[0]), "r"(b[1]));
}
__device__ __forceinline__ void ldsm4(unsigned* r, uint32_t addr) {
    asm volatile(
        "ldmatrix.sync.aligned.m8n8.x4.shared.b16 {%0,%1,%2,%3}, [%4];"
        : "=r"(r[0]), "=r"(r[1]), "=r"(r[2]), "=r"(r[3]) : "r"(addr));
}
__device__ __forceinline__ unsigned sptr(const void* p) {
    return (unsigned)__cvta_generic_to_shared(p);
}
#define CPA16(dst, src) asm volatile("cp.async.ca.shared.global [%0], [%1], 16;\n" :: "r"(dst), "l"(src))
#define CPCOMMIT()      asm volatile("cp.async.commit_group;\n")
#define CPWAIT1()       asm volatile("cp.async.wait_group 1;\n" ::: "memory")

// ---------------------------- GroupNorm --------------------------------------
__global__ void groupnorm_kernel(const float* __restrict__ x,
                                 const float* __restrict__ gw,
                                 const float* __restrict__ gb) {
    int b = blockIdx.x >> 5;
    int g = blockIdx.x & 31;
    const float4* xp = (const float4*)(x    + ((size_t)b * CCH + g * CPG) * HW);
    float4*       op = (float4*)      (g_hn + ((size_t)b * CCH + g * CPG) * HW);
    int tid = threadIdx.x;

    float s = 0.f, ss = 0.f;
    for (int i = tid; i < GRPELEM / 4; i += 256) {
        float4 v = xp[i];
        s  += v.x + v.y + v.z + v.w;
        ss += v.x * v.x + v.y * v.y + v.z * v.z + v.w * v.w;
    }
    __shared__ float shs[8], shss[8];
    #pragma unroll
    for (int o = 16; o; o >>= 1) {
        s  += __shfl_xor_sync(0xffffffffu, s,  o);
        ss += __shfl_xor_sync(0xffffffffu, ss, o);
    }
    if ((tid & 31) == 0) { shs[tid >> 5] = s; shss[tid >> 5] = ss; }
    __syncthreads();
    __shared__ float sm, sr;
    if (tid == 0) {
        float S = 0.f, SS = 0.f;
        #pragma unroll
        for (int i = 0; i < 8; i++) { S += shs[i]; SS += shss[i]; }
        float mean = S / (float)GRPELEM;
        float var  = SS / (float)GRPELEM - mean * mean;
        sm = mean;
        sr = rsqrtf(var + 1e-6f);
    }
    __syncthreads();
    float mean = sm, rstd = sr;
    for (int i = tid; i < GRPELEM / 4; i += 256) {
        int cl = i >> 10;
        float sc = gw[g * CPG + cl] * rstd;
        float sh = gb[g * CPG + cl] - mean * sc;
        float4 v = xp[i];
        v.x = v.x * sc + sh; v.y = v.y * sc + sh;
        v.z = v.z * sc + sh; v.w = v.w * sc + sh;
        op[i] = v;
    }
}

// ------- transpose normed activations: g_hn [c][n] fp32 -> g_hb [n][c] bf16 --
__global__ void hb_transpose_kernel() {
    __shared__ float tile[32][33];
    int b = blockIdx.z;
    int c0 = blockIdx.y * 32, n0 = blockIdx.x * 32;
    int tx = threadIdx.x & 31, ty = threadIdx.x >> 5;   // 256 thr: ty 0..7
    const float* src = g_hn + ((size_t)b * CCH + c0) * HW + n0;
    #pragma unroll
    for (int r = ty; r < 32; r += 8)
        tile[r][tx] = src[(size_t)r * HW + tx];
    __syncthreads();
    __nv_bfloat16* dst = g_hb + ((size_t)b * HW + n0) * CCH + c0;
    #pragma unroll
    for (int r = ty; r < 32; r += 8)
        dst[(size_t)r * CCH + tx] = __float2bfloat16(tile[tx][r]);
}

// ------- convert weights to bf16: g_wb[which] = bf16(w) ----------------------
__global__ void wcvt_kernel(const float* __restrict__ wq, const float* __restrict__ wk,
                            const float* __restrict__ wv, const float* __restrict__ wp) {
    int idx = blockIdx.x * 256 + threadIdx.x;         // float4 index
    int which = idx / (CCH * CCH / 4);
    int off   = idx % (CCH * CCH / 4);
    const float* src = which == 0 ? wq : which == 1 ? wk : which == 2 ? wv : wp;
    float4 v = ((const float4*)src)[off];
    __nv_bfloat162* d = (__nv_bfloat162*)(g_wb + (size_t)which * CCH * CCH) + off * 2;
    d[0] = __floats2bfloat162_rn(v.x, v.y);
    d[1] = __floats2bfloat162_rn(v.z, v.w);
}

// ---- bf16 mainloop body: warp tile 64x64, k-chunk 64, ldmatrix frags --------
#define BF16_CHUNK_MMAS(acc, At_s, Bt_s)  do {                                 \
    _Pragma("unroll")                                                          \
    for (int kk = 0; kk < 4; kk++) {                                           \
        unsigned af[4][4], bf[8][2];                                           \
        _Pragma("unroll")                                                      \
        for (int mi = 0; mi < 4; mi++)                                         \
            ldsm4(af[mi], (At_s) +                                             \
                  4u * ((wm + mi * 16 + a_row) * OROWW + kk * 8 + a_kw));      \
        _Pragma("unroll")                                                      \
        for (int njp = 0; njp < 4; njp++)                                      \
            ldsm4(&bf[2 * njp][0], (Bt_s) +                                    \
                  4u * ((wn + njp * 16 + b_row) * OROWW + kk * 8 + b_kw));     \
        _Pragma("unroll")                                                      \
        for (int mi = 0; mi < 4; mi++)                                         \
            _Pragma("unroll")                                                  \
            for (int nj = 0; nj < 8; nj++) mma16((acc)[mi][nj], af[mi], bf[nj]); \
    } } while (0)

// A tile: 128 rows x 64 bf16; B tile: 256 rows x 64 bf16; 144 B pitch
#define BF16_LOAD_STAGE(st, Ag, Astr, Bg, Bstr, ck) do {                       \
    const __nv_bfloat16* as = (Ag) + (size_t)lrow * (Astr) + (ck) * 64 + lh * 32; \
    _Pragma("unroll")                                                          \
    for (int j = 0; j < 4; j++)                                                \
        CPA16((st) + lrow * 144 + lh * 64 + j * 16, as + j * 8);               \
    _Pragma("unroll")                                                          \
    for (int rr = 0; rr < 2; rr++) {                                           \
        int brr = lrow + rr * 128;                                             \
        const __nv_bfloat16* bs = (Bg) + (size_t)brr * (Bstr) + (ck) * 64 + lh * 32; \
        _Pragma("unroll")                                                      \
        for (int j = 0; j < 4; j++)                                            \
            CPA16((st) + ASTG_B + brr * 144 + lh * 64 + j * 16, bs + j * 8);   \
    } } while (0)

#define BF16_PREAMBLE()                                                        \
    int tid = threadIdx.x;                                                     \
    int lane = tid & 31, warp = tid >> 5;                                      \
    int g = lane >> 2, tig = lane & 3;                                         \
    int wm = (warp >> 2) * 64, wn = (warp & 3) * 64;                           \
    int lrow = tid >> 1, lh = tid & 1;                                         \
    int mat = lane >> 3, mr = lane & 7;                                        \
    int a_row = ((mat & 1) << 3) + mr, a_kw = (mat >> 1) << 2;                 \
    int b_row = ((mat >> 1) << 3) + mr, b_kw = (mat & 1) << 2;                 \
    (void)g; (void)tig;                                                        \
    float acc[4][8][4];                                                        \
    _Pragma("unroll")                                                          \
    for (int i = 0; i < 4; i++)                                                \
        _Pragma("unroll")                                                      \
        for (int j = 0; j < 8; j++)                                            \
            _Pragma("unroll")                                                  \
            for (int t = 0; t < 4; t++) acc[i][j][t] = 0.f;

// -------- QKV GEMM (bf16, merged): C[m,n] = sum_c Hb[m,c]*W[n,c] + bias[n] ---
// which 0 -> g_q bf16 [i][c], 1 -> g_k bf16 [j][c], 2 -> g_vt fp32 [c][i]
__global__ __launch_bounds__(256, 1)
void qkv_bf16_kernel(const float* __restrict__ bq, const float* __restrict__ bk,
                     const float* __restrict__ bv) {
    extern __shared__ unsigned ssm[];
    int b = blockIdx.z;
    int which = blockIdx.y >> 1;
    int n0 = (blockIdx.y & 1) * 256, m0 = blockIdx.x * 128;
    const __nv_bfloat16* Ag = g_hb + (size_t)b * HW * CCH + (size_t)m0 * CCH;
    const __nv_bfloat16* Bg = g_wb + (size_t)which * CCH * CCH + (size_t)n0 * CCH;
    const float* bias = which == 0 ? bq : which == 1 ? bk : bv;
    uint32_t sbase = sptr(ssm);
    BF16_PREAMBLE();

    const int NC = CCH / 64;   // 8
    #pragma unroll
    for (int s = 0; s < 2; s++) {
        BF16_LOAD_STAGE(sbase + s * STG_B, Ag, CCH, Bg, CCH, s);
        CPCOMMIT();
    }
    for (int kt = 0; kt < NC; kt++) {
        CPWAIT1();
        __syncthreads();
        uint32_t At_s = sbase + (kt % 3) * STG_B;
        uint32_t Bt_s = At_s + ASTG_B;
        BF16_CHUNK_MMAS(acc, At_s, Bt_s);
        int nk = kt + 2;
        if (nk < NC) {
            BF16_LOAD_STAGE(sbase + (nk % 3) * STG_B, Ag, CCH, Bg, CCH, nk);
        }
        CPCOMMIT();
    }
    if (which == 2) {
        float* Vt = g_vt + (size_t)b * CCH * HW;
        #pragma unroll
        for (int mi = 0; mi < 4; mi++)
            #pragma unroll
            for (int nj = 0; nj < 8; nj++) {
                int r = m0 + wm + mi * 16 + g;
                int c = n0 + wn + nj * 8 + 2 * tig;
                float bv0 = bias[c], bv1 = bias[c + 1];
                Vt[(size_t)c * HW + r]           = acc[mi][nj][0] + bv0;
                Vt[(size_t)(c + 1) * HW + r]     = acc[mi][nj][1] + bv1;
                Vt[(size_t)c * HW + r + 8]       = acc[mi][nj][2] + bv0;
                Vt[(size_t)(c + 1) * HW + r + 8] = acc[mi][nj][3] + bv1;
            }
    } else {
        __nv_bfloat16* Cp = (which == 0 ? g_q : g_k) + (size_t)b * HW * CCH;
        #pragma unroll
        for (int mi = 0; mi < 4; mi++)
            #pragma unroll
            for (int nj = 0; nj < 8; nj++) {
                int r = m0 + wm + mi * 16 + g;
                int c = n0 + wn + nj * 8 + 2 * tig;
                float bv0 = bias[c], bv1 = bias[c + 1];
                *(__nv_bfloat162*)&Cp[(size_t)r * CCH + c] =
                    __floats2bfloat162_rn(acc[mi][nj][0] + bv0, acc[mi][nj][1] + bv1);
                *(__nv_bfloat162*)&Cp[(size_t)(r + 8) * CCH + c] =
                    __floats2bfloat162_rn(acc[mi][nj][2] + bv0, acc[mi][nj][3] + bv1);
            }
    }
}

// -------- Scores (bf16): E'[j,i] = exp(scale * K_j . Q_i) -> bf16 ------------
__global__ __launch_bounds__(256, 1)
void scores_bf16_kernel() {
    extern __shared__ unsigned ssm[];
    int b = blockIdx.z;
    const __nv_bfloat16* Ag = g_k + (size_t)b * HW * CCH + (size_t)(blockIdx.x * 128) * CCH;
    const __nv_bfloat16* Bg = g_q + (size_t)b * HW * CCH + (size_t)(blockIdx.y * 256) * CCH;
    uint32_t sbase = sptr(ssm);
    BF16_PREAMBLE();

    const int NC = CCH / 64;   // 8
    #pragma unroll
    for (int s = 0; s < 2; s++) {
        BF16_LOAD_STAGE(sbase + s * STG_B, Ag, CCH, Bg, CCH, s);
        CPCOMMIT();
    }
    for (int kt = 0; kt < NC; kt++) {
        CPWAIT1();
        __syncthreads();
        uint32_t At_s = sbase + (kt % 3) * STG_B;
        uint32_t Bt_s = At_s + ASTG_B;
        BF16_CHUNK_MMAS(acc, At_s, Bt_s);
        int nk = kt + 2;
        if (nk < NC) {
            BF16_LOAD_STAGE(sbase + (nk % 3) * STG_B, Ag, CCH, Bg, CCH, nk);
        }
        CPCOMMIT();
    }
    const float scale = 0.04419417382415922f;   // 512^-0.5
    __nv_bfloat16* Cp = g_s + (size_t)b * HW * HW;
    int m0 = blockIdx.x * 128, n0 = blockIdx.y * 256;
    #pragma unroll
    for (int mi = 0; mi < 4; mi++)
        #pragma unroll
        for (int nj = 0; nj < 8; nj++) {
            int r = m0 + wm + mi * 16 + g;
            int c = n0 + wn + nj * 8 + 2 * tig;
            *(__nv_bfloat162*)&Cp[(size_t)r * HW + c] =
                __floats2bfloat162_rn(__expf(acc[mi][nj][0] * scale),
                                      __expf(acc[mi][nj][1] * scale));
            *(__nv_bfloat162*)&Cp[(size_t)(r + 8) * HW + c] =
                __floats2bfloat162_rn(__expf(acc[mi][nj][2] * scale),
                                      __expf(acc[mi][nj][3] * scale));
        }
}

// ------- column sums of E' stage 1: each CTA sums 64 rows x 512 cols ---------
__global__ void zcolsum_kernel() {
    int b = blockIdx.z;
    const __nv_bfloat162* S = (const __nv_bfloat162*)(g_s + (size_t)b * HW * HW);
    int t = threadIdx.x;
    size_t rowstride = HW / 2;
    const __nv_bfloat162* p = S + (size_t)(blockIdx.y * ZROWBLK) * rowstride
                                + blockIdx.x * 256 + t;
    float sx[16], sy[16];
    #pragma unroll
    for (int u = 0; u < 16; u++) { sx[u] = 0.f; sy[u] = 0.f; }
    #pragma unroll
    for (int jj = 0; jj < ZROWBLK / 16; jj++) {
        #pragma unroll
        for (int u = 0; u < 16; u++) {
            float2 v = __bfloat1622float2(p[(size_t)(jj * 16 + u) * rowstride]);
            sx[u] += v.x; sy[u] += v.y;
        }
    }
    float fx = 0.f, fy = 0.f;
    #pragma unroll
    for (int u = 0; u < 16; u++) { fx += sx[u]; fy += sy[u]; }
    float* zp = g_zp + ((size_t)(b * (HW / ZROWBLK) + blockIdx.y)) * HW
              + (size_t)(blockIdx.x * 256 + t) * 2;
    zp[0] = fx; zp[1] = fy;
}

// ------- stage 2: combine partials, reciprocal -------------------------------
__global__ void zfin_kernel() {
    int idx = blockIdx.x * 256 + threadIdx.x;   // < BATCH*HW
    int b = idx >> 12, i = idx & (HW - 1);
    const float* zp = g_zp + (size_t)b * (HW / ZROWBLK) * HW + i;
    float s0 = 0.f, s1 = 0.f, s2 = 0.f, s3 = 0.f;
    #pragma unroll
    for (int p = 0; p < HW / ZROWBLK; p += 4) {
        s0 += zp[(size_t)(p + 0) * HW];
        s1 += zp[(size_t)(p + 1) * HW];
        s2 += zp[(size_t)(p + 2) * HW];
        s3 += zp[(size_t)(p + 3) * HW];
    }
    g_z[idx] = 1.f / ((s0 + s1) + (s2 + s3));
}

// ------- V-hat: g_vb[c][i] = bf16(g_vt[c][i] * g_z[i]) -----------------------
__global__ void vscale_kernel() {
    size_t idx4 = (size_t)blockIdx.x * 256 + threadIdx.x;
    int b = (int)(idx4 / ((size_t)CCH * (HW / 4)));
    size_t rem = idx4 - (size_t)b * CCH * (HW / 4);
    int i4 = (int)(rem % (HW / 4));
    float4 v = ((const float4*)g_vt)[idx4];
    float4 z = ((const float4*)g_z)[(size_t)b * (HW / 4) + i4];
    __nv_bfloat162* o = ((__nv_bfloat162*)g_vb) + idx4 * 2;
    o[0] = __floats2bfloat162_rn(v.x * z.x, v.y * z.y);
    o[1] = __floats2bfloat162_rn(v.z * z.z, v.w * z.w);
}

// ------ O GEMM (bf16): O[j,c] = sum_i E'[j,i] * Vhat[c,i] -> bf16 ------------
__global__ __launch_bounds__(256, 1)
void o_bf16_kernel() {
    extern __shared__ unsigned osm[];
    int b = blockIdx.z;
    const __nv_bfloat16* Ag = g_s  + (size_t)b * HW * HW + (size_t)(blockIdx.x * 128) * HW;
    const __nv_bfloat16* Bg = g_vb + (size_t)b * CCH * HW + (size_t)(blockIdx.y * 256) * HW;
    uint32_t sbase = sptr(osm);
    BF16_PREAMBLE();

    const int NC = HW / 64;   // 64
    #pragma unroll
    for (int s = 0; s < 2; s++) {
        BF16_LOAD_STAGE(sbase + s * STG_B, Ag, HW, Bg, HW, s);
        CPCOMMIT();
    }
    for (int kt = 0; kt < NC; kt++) {
        CPWAIT1();
        __syncthreads();
        uint32_t At_s = sbase + (kt % 3) * STG_B;
        uint32_t Bt_s = At_s + ASTG_B;
        BF16_CHUNK_MMAS(acc, At_s, Bt_s);
        int nk = kt + 2;
        if (nk < NC) {
            BF16_LOAD_STAGE(sbase + (nk % 3) * STG_B, Ag, HW, Bg, HW, nk);
        }
        CPCOMMIT();
    }
    __nv_bfloat16* Cp = g_ob + (size_t)b * HW * CCH;
    int m0 = blockIdx.x * 128, n0 = blockIdx.y * 256;
    #pragma unroll
    for (int mi = 0; mi < 4; mi++)
        #pragma unroll
        for (int nj = 0; nj < 8; nj++) {
            int r = m0 + wm + mi * 16 + g;
            int c = n0 + wn + nj * 8 + 2 * tig;
            *(__nv_bfloat162*)&Cp[(size_t)r * CCH + c] =
                __floats2bfloat162_rn(acc[mi][nj][0], acc[mi][nj][1]);
            *(__nv_bfloat162*)&Cp[(size_t)(r + 8) * CCH + c] =
                __floats2bfloat162_rn(acc[mi][nj][2], acc[mi][nj][3]);
        }
}

// ------ Proj+residual (bf16): out[o,m] = x[o,m] + sum_c O[m,c]Wp[o,c]+bp[o] --
__global__ __launch_bounds__(256, 1)
void proj_bf16_kernel(const float* __restrict__ bp,
                      const float* __restrict__ x, float* __restrict__ out) {
    extern __shared__ unsigned ssm[];
    int b = blockIdx.z;
    int n0 = blockIdx.y * 256, m0 = blockIdx.x * 128;
    const __nv_bfloat16* Ag = g_ob + (size_t)b * HW * CCH + (size_t)m0 * CCH;
    const __nv_bfloat16* Bg = g_wb + (size_t)3 * CCH * CCH + (size_t)n0 * CCH;
    const float* xb = x   + (size_t)b * CCH * HW;
    float* ob = out + (size_t)b * CCH * HW;
    uint32_t sbase = sptr(ssm);
    BF16_PREAMBLE();

    const int NC = CCH / 64;   // 8
    #pragma unroll
    for (int s = 0; s < 2; s++) {
        BF16_LOAD_STAGE(sbase + s * STG_B, Ag, CCH, Bg, CCH, s);
        CPCOMMIT();
    }
    for (int kt = 0; kt < NC; kt++) {
        CPWAIT1();
        __syncthreads();
        uint32_t At_s = sbase + (kt % 3) * STG_B;
        uint32_t Bt_s = At_s + ASTG_B;
        BF16_CHUNK_MMAS(acc, At_s, Bt_s);
        int nk = kt + 2;
        if (nk < NC) {
            BF16_LOAD_STAGE(sbase + (nk % 3) * STG_B, Ag, CCH, Bg, CCH, nk);
        }
        CPCOMMIT();
    }
    #pragma unroll
    for (int nj = 0; nj < 8; nj++) {
        int c0 = n0 + wn + nj * 8 + 2 * tig;
        float bv0 = bp[c0], bv1 = bp[c0 + 1];
        #pragma unroll
        for (int mi = 0; mi < 4; mi++) {
            int r = m0 + wm + mi * 16 + g;
            ob[(size_t)c0 * HW + r]           = xb[(size_t)c0 * HW + r]           + acc[mi][nj][0] + bv0;
            ob[(size_t)(c0 + 1) * HW + r]     = xb[(size_t)(c0 + 1) * HW + r]     + acc[mi][nj][1] + bv1;
            ob[(size_t)c0 * HW + r + 8]       = xb[(size_t)c0 * HW + r + 8]       + acc[mi][nj][2] + bv0;
            ob[(size_t)(c0 + 1) * HW + r + 8] = xb[(size_t)(c0 + 1) * HW + r + 8] + acc[mi][nj][3] + bv1;
        }
    }
}

// ------------------------------ launch ---------------------------------------
extern "C" void kernel_launch(void* const* d_in, const int* in_sizes, int n_in,
                              void* d_out, int out_size) {
    const float* x  = (const float*)d_in[0];
    const float* nw = (const float*)d_in[1];
    const float* nb = (const float*)d_in[2];
    const float* wq = (const float*)d_in[3];
    const float* bq = (const float*)d_in[4];
    const float* wk = (const float*)d_in[5];
    const float* bk = (const float*)d_in[6];
    const float* wv = (const float*)d_in[7];
    const float* bv = (const float*)d_in[8];
    const float* wp = (const float*)d_in[9];
    const float* bp = (const float*)d_in[10];
    float* out = (float*)d_out;

    static int attr_done = 0;
    if (!attr_done) {
        cudaFuncSetAttribute(qkv_bf16_kernel,
                             cudaFuncAttributeMaxDynamicSharedMemorySize, DYN_B);
        cudaFuncSetAttribute(scores_bf16_kernel,
                             cudaFuncAttributeMaxDynamicSharedMemorySize, DYN_B);
        cudaFuncSetAttribute(o_bf16_kernel,
                             cudaFuncAttributeMaxDynamicSharedMemorySize, DYN_B);
        cudaFuncSetAttribute(proj_bf16_kernel,
                             cudaFuncAttributeMaxDynamicSharedMemorySize, DYN_B);
        attr_done = 1;
    }

    groupnorm_kernel<<<BATCH * NGRP, 256>>>(x, nw, nb);

    wcvt_kernel<<<(4 * CCH * CCH / 4) / 256, 256>>>(wq, wk, wv, wp);

    dim3 gtr(HW / 32, CCH / 32, BATCH);         // 128 x 16 x 2
    hb_transpose_kernel<<<gtr, 256>>>();

    dim3 gqkv(HW / 128, 3 * CCH / 256, BATCH);  // 32 x 6 x 2
    qkv_bf16_kernel<<<gqkv, 256, DYN_B>>>(bq, bk, bv);

    dim3 gsc(HW / 128, HW / 256, BATCH);        // 32 x 16 x 2
    scores_bf16_kernel<<<gsc, 256, DYN_B>>>();

    dim3 gzc(HW / 512, HW / ZROWBLK, BATCH);    // 8 x 64 x 2
    zcolsum_kernel<<<gzc, 256>>>();
    zfin_kernel<<<(BATCH * HW) / 256, 256>>>();
    vscale_kernel<<<(BATCH * CCH * HW) / (4 * 256), 256>>>();

    dim3 go(HW / 128, CCH / 256, BATCH);        // 32 x 2 x 2
    o_bf16_kernel<<<go, 256, DYN_B>>>();

    proj_bf16_kernel<<<go, 256, DYN_B>>>(bp, x, out);
}